// round 8
// baseline (speedup 1.0000x reference)
#include <cuda_runtime.h>
#include <cuda_bf16.h>
#include <stdint.h>
#include <math.h>

#define NN 10000
#define EE 320000
#define HH 256
#define NHD 8

// ---------------- scratch (static device globals; no runtime alloc) --------
__device__ float g_S1[NN * HH];
__device__ float g_T1[NN * HH];
__device__ float g_Sv[NN * HH];
__device__ float g_e1[(size_t)EE * HH];
__device__ float g_e2[(size_t)EE * HH];
__device__ float g_logits[(size_t)EE * NHD];
__device__ float g_agg[NN * HH];
__device__ int   g_deg[NN];
__device__ int   g_cur[NN];
__device__ int   g_off[NN + 1];
__device__ int   g_elist[EE];
__device__ int   g_dst[EE];
__device__ int   g_src[EE];
__device__ int   g_is64;

__device__ __forceinline__ float gelu_f(float x) {
    return 0.5f * x * (1.0f + erff(x * 0.7071067811865476f));
}

__device__ __forceinline__ unsigned int f2tf32(float f) {
    unsigned int r;
    asm("cvt.rna.tf32.f32 %0, %1;" : "=r"(r) : "f"(f));
    return r;
}

// m16n8k8 tf32 mma (row.col), fp32 accumulate
__device__ __forceinline__ void mma_tf32(float* c, const unsigned int* a,
                                         const unsigned int* b) {
    asm volatile(
        "mma.sync.aligned.m16n8k8.row.col.f32.tf32.tf32.f32 "
        "{%0,%1,%2,%3}, {%4,%5,%6,%7}, {%8,%9}, {%0,%1,%2,%3};"
        : "+f"(c[0]), "+f"(c[1]), "+f"(c[2]), "+f"(c[3])
        : "r"(a[0]), "r"(a[1]), "r"(a[2]), "r"(a[3]), "r"(b[0]), "r"(b[1]));
}

// ---------------- tf32 mma.sync GEMM: C = act(A @ W^T + bias + gathers) ----
// CTA tile 64 x 128 (grid.y over 2 N-halves). 256 thr, warp grid 2x4, warp
// tile 32x32. K = 256 in 16 double-buffered chunks of 16.
// act: 0 none, 1 relu, 2 gelu, 3 = relu + fused logits projection (no C)
#define KC 16
#define ASTR 20                       // smem row stride (floats)
#define ABUF (64 * ASTR)              // 1280 floats
#define BBUF (128 * ASTR)             // 2560 floats
#define BUFF (ABUF + BBUF)            // 3840 floats
#define SMEM_GEMM (2 * BUFF * 4)      // 30720 B
#define SMEM_ACT3 ((64 * 132 + 1024 + 128) * 4)   // 38016 B

__global__ void __launch_bounds__(256, 3) mma_gemm(
    const float* __restrict__ A, int lda,
    const float* __restrict__ W, int ldw,
    const float* __restrict__ bias,
    const float* __restrict__ add1, const int* __restrict__ idx1,
    const float* __restrict__ add2, const int* __restrict__ idx2,
    float* __restrict__ C, int M, int act,
    const float* __restrict__ Wb3, float* __restrict__ logits)
{
    extern __shared__ float smf[];
    unsigned int* sm = reinterpret_cast<unsigned int*>(smf);

    const int tid = threadIdx.x;
    const int wid = tid >> 5;
    const int lane = tid & 31;
    const int warp_m = wid & 1;       // 2 warps over 64 M-rows (32 each)
    const int warp_n = wid >> 1;      // 4 warps over 128 N-cols (32 each)
    const int qr = lane >> 2;
    const int qc = lane & 3;
    const int m0 = blockIdx.x * 64;
    const int n0 = blockIdx.y * 128;

    float c[2][4][4];
#pragma unroll
    for (int i = 0; i < 2; i++)
#pragma unroll
        for (int j = 0; j < 4; j++)
#pragma unroll
            for (int q = 0; q < 4; q++) c[i][j][q] = 0.f;

    float4 ra, rb0, rb1;
    const int lr_a = tid >> 2, lf_a = tid & 3;     // A: 64 rows x 4 f4
    auto load_regs = [&](int kc) {
        const int kcol = kc * KC;
        ra = make_float4(0.f, 0.f, 0.f, 0.f);
        if (m0 + lr_a < M)
            ra = *reinterpret_cast<const float4*>(
                A + (size_t)(m0 + lr_a) * lda + kcol + lf_a * 4);
        rb0 = *reinterpret_cast<const float4*>(
            W + (size_t)(n0 + lr_a) * ldw + kcol + lf_a * 4);
        rb1 = *reinterpret_cast<const float4*>(
            W + (size_t)(n0 + 64 + lr_a) * ldw + kcol + lf_a * 4);
    };
    auto store_regs = [&](int buf) {
        unsigned int* sA = sm + buf * BUFF;
        unsigned int* sB = sA + ABUF;
        uint4 t;
        t.x = f2tf32(ra.x); t.y = f2tf32(ra.y);
        t.z = f2tf32(ra.z); t.w = f2tf32(ra.w);
        *reinterpret_cast<uint4*>(sA + lr_a * ASTR + lf_a * 4) = t;
        t.x = f2tf32(rb0.x); t.y = f2tf32(rb0.y);
        t.z = f2tf32(rb0.z); t.w = f2tf32(rb0.w);
        *reinterpret_cast<uint4*>(sB + lr_a * ASTR + lf_a * 4) = t;
        t.x = f2tf32(rb1.x); t.y = f2tf32(rb1.y);
        t.z = f2tf32(rb1.z); t.w = f2tf32(rb1.w);
        *reinterpret_cast<uint4*>(sB + (64 + lr_a) * ASTR + lf_a * 4) = t;
    };
    auto mma_ks = [&](int b, int ks) {
        const unsigned int* sA = sm + b * BUFF;
        const unsigned int* sB = sA + ABUF;
        const int k0 = ks * 8;
        unsigned int af[2][4], bf[4][2];
#pragma unroll
        for (int mt = 0; mt < 2; mt++) {
            int base = (warp_m * 32 + mt * 16 + qr) * ASTR + k0 + qc;
            af[mt][0] = sA[base];
            af[mt][1] = sA[base + 8 * ASTR];
            af[mt][2] = sA[base + 4];
            af[mt][3] = sA[base + 8 * ASTR + 4];
        }
#pragma unroll
        for (int nt = 0; nt < 4; nt++) {
            int base = (warp_n * 32 + nt * 8 + qr) * ASTR + k0 + qc;
            bf[nt][0] = sB[base];
            bf[nt][1] = sB[base + 4];
        }
#pragma unroll
        for (int mt = 0; mt < 2; mt++)
#pragma unroll
            for (int nt = 0; nt < 4; nt++)
                mma_tf32(c[mt][nt], af[mt], bf[nt]);
    };

    load_regs(0);
    store_regs(0);
    __syncthreads();

#pragma unroll 1
    for (int kc = 0; kc < 16; kc++) {
        const int b = kc & 1;
        if (kc < 15) load_regs(kc + 1);
        mma_ks(b, 0);
        if (kc < 15) store_regs(b ^ 1);
        mma_ks(b, 1);
        __syncthreads();
    }

    if (act == 3) {
        // stage 64x132 in smem, then fused relu + logits projection
        float* stage = smf;
#pragma unroll
        for (int mt = 0; mt < 2; mt++)
#pragma unroll
            for (int nt = 0; nt < 4; nt++) {
                int row = warp_m * 32 + mt * 16 + qr;
                int col = warp_n * 32 + nt * 8 + qc * 2;
                *reinterpret_cast<float2*>(stage + row * 132 + col) =
                    make_float2(c[mt][nt][0], c[mt][nt][1]);
                *reinterpret_cast<float2*>(stage + (row + 8) * 132 + col) =
                    make_float2(c[mt][nt][2], c[mt][nt][3]);
            }
        float* sW3 = smf + 64 * 132;
        float* sb = sW3 + 1024;
        for (int i = tid; i < 1024; i += 256)
            sW3[i] = Wb3[(i >> 7) * 256 + n0 + (i & 127)];
        if (tid < 128) sb[tid] = bias[n0 + tid];
        __syncthreads();

        int row = tid >> 2, q = tid & 3;
        float acc[NHD];
#pragma unroll
        for (int h = 0; h < NHD; h++) acc[h] = 0.f;
#pragma unroll 4
        for (int cc = 0; cc < 32; cc++) {
            int col = q + cc * 4;
            float v = fmaxf(stage[row * 132 + col] + sb[col], 0.f);
#pragma unroll
            for (int h = 0; h < NHD; h++) acc[h] += v * sW3[h * 128 + col];
        }
#pragma unroll
        for (int h = 0; h < NHD; h++) {
            acc[h] += __shfl_xor_sync(0xffffffffu, acc[h], 1);
            acc[h] += __shfl_xor_sync(0xffffffffu, acc[h], 2);
        }
        if (q == 0) {
            int m = m0 + row;
#pragma unroll
            for (int h = 0; h < NHD; h++)
                atomicAdd(&logits[(size_t)m * NHD + h],
                          acc[h] * 0.17677669529663687f);
        }
        return;
    }

    // ---- direct-STG fused epilogue (8 full sectors per STG.64) ----
#pragma unroll
    for (int mt = 0; mt < 2; mt++) {
        int mlo = m0 + warp_m * 32 + mt * 16 + qr;
        int mhi = mlo + 8;
        const float* r1lo = nullptr; const float* r1hi = nullptr;
        const float* r2lo = nullptr; const float* r2hi = nullptr;
        if (add1) {
            if (mlo < M) r1lo = add1 + (size_t)idx1[mlo] * 256;
            if (mhi < M) r1hi = add1 + (size_t)idx1[mhi] * 256;
        }
        if (add2) {
            if (mlo < M) r2lo = add2 + (size_t)idx2[mlo] * 256;
            if (mhi < M) r2hi = add2 + (size_t)idx2[mhi] * 256;
        }
#pragma unroll
        for (int nt = 0; nt < 4; nt++) {
            int n = n0 + warp_n * 32 + nt * 8 + qc * 2;
            float bx = 0.f, by = 0.f;
            if (bias) { bx = __ldg(bias + n); by = __ldg(bias + n + 1); }
            if (mlo < M) {
                float vx = c[mt][nt][0] + bx, vy = c[mt][nt][1] + by;
                if (r1lo) { float2 a = *reinterpret_cast<const float2*>(r1lo + n); vx += a.x; vy += a.y; }
                if (r2lo) { float2 a = *reinterpret_cast<const float2*>(r2lo + n); vx += a.x; vy += a.y; }
                if (act == 1) { vx = fmaxf(vx, 0.f); vy = fmaxf(vy, 0.f); }
                else if (act == 2) { vx = gelu_f(vx); vy = gelu_f(vy); }
                *reinterpret_cast<float2*>(C + (size_t)mlo * 256 + n) =
                    make_float2(vx, vy);
            }
            if (mhi < M) {
                float vx = c[mt][nt][2] + bx, vy = c[mt][nt][3] + by;
                if (r1hi) { float2 a = *reinterpret_cast<const float2*>(r1hi + n); vx += a.x; vy += a.y; }
                if (r2hi) { float2 a = *reinterpret_cast<const float2*>(r2hi + n); vx += a.x; vy += a.y; }
                if (act == 1) { vx = fmaxf(vx, 0.f); vy = fmaxf(vy, 0.f); }
                else if (act == 2) { vx = gelu_f(vx); vy = gelu_f(vy); }
                *reinterpret_cast<float2*>(C + (size_t)mhi * 256 + n) =
                    make_float2(vx, vy);
            }
        }
    }
}

// ---------------- logits init: bb3 broadcast * 1/sqrt(d) -------------------
__global__ void k_initlog(const float* __restrict__ bb3,
                          float* __restrict__ logits) {
    int i = blockIdx.x * 256 + threadIdx.x;
    if (i < EE * NHD)
        logits[i] = __ldg(bb3 + (i & 7)) * 0.17677669529663687f;
}

// ---------------- index dtype sniff + normalize ----------------------------
__global__ void k_sniff(const int* __restrict__ buf) {
    __shared__ int nz;
    if (threadIdx.x == 0) nz = 0;
    __syncthreads();
    int w = buf[threadIdx.x * 2 + 1];
    if (w != 0) atomicOr(&nz, 1);
    __syncthreads();
    if (threadIdx.x == 0) g_is64 = nz ? 0 : 1;
}

__global__ void k_convert(const void* __restrict__ buf,
                          int* __restrict__ dst, int* __restrict__ src) {
    int e = blockIdx.x * 256 + threadIdx.x;
    if (e >= EE) return;
    if (g_is64) {
        const long long* p = (const long long*)buf;
        dst[e] = (int)p[e];
        src[e] = (int)p[EE + e];
    } else {
        const int* p = (const int*)buf;
        dst[e] = p[e];
        src[e] = p[EE + e];
    }
}

// ---------------- CSR build -------------------------------------------------
__global__ void k_zero(int* a, int* b, int n) {
    int i = blockIdx.x * blockDim.x + threadIdx.x;
    if (i < n) { a[i] = 0; b[i] = 0; }
}

__global__ void k_count(const int* __restrict__ dst, int* __restrict__ deg) {
    int e = blockIdx.x * 256 + threadIdx.x;
    if (e < EE) atomicAdd(&deg[dst[e]], 1);
}

__global__ void __launch_bounds__(1024) k_scan(
    const int* __restrict__ deg, int* __restrict__ off)
{
    __shared__ int ssum[1024];
    const int t = threadIdx.x;
    const int ITEMS = 10;
    int base = t * ITEMS;
    int loc[ITEMS];
    int s = 0;
#pragma unroll
    for (int i = 0; i < ITEMS; i++) {
        int v = (base + i < NN) ? deg[base + i] : 0;
        loc[i] = s;
        s += v;
    }
    ssum[t] = s;
    __syncthreads();
    for (int d = 1; d < 1024; d <<= 1) {
        int v = (t >= d) ? ssum[t - d] : 0;
        __syncthreads();
        if (t >= d) ssum[t] += v;
        __syncthreads();
    }
    int excl = (t == 0) ? 0 : ssum[t - 1];
#pragma unroll
    for (int i = 0; i < ITEMS; i++)
        if (base + i < NN) off[base + i] = excl + loc[i];
    if (t == 0) off[NN] = ssum[1023];
}

__global__ void k_fill(const int* __restrict__ dst,
                       const int* __restrict__ off, int* __restrict__ cur,
                       int* __restrict__ elist)
{
    int e = blockIdx.x * 256 + threadIdx.x;
    if (e < EE) {
        int d = dst[e];
        int p = off[d] + atomicAdd(&cur[d], 1);
        elist[p] = e;
    }
}

// ---------------- per-node softmax + weighted aggregation ------------------
__global__ void __launch_bounds__(256) k_softmax_agg(
    const float* __restrict__ logits, const float* __restrict__ V,
    const int* __restrict__ off, const int* __restrict__ elist,
    float* __restrict__ agg)
{
    int n = blockIdx.x;
    int tid = threadIdx.x;
    int lane = tid & 31;
    int w = tid >> 5;

    int s = off[n];
    int deg = off[n + 1] - s;
    if (deg == 0) { agg[(size_t)n * HH + tid] = 0.f; return; }

    __shared__ float s_m[NHD], s_d[NHD];
    __shared__ int s_eid[64];

    float mx = -INFINITY;
    for (int i = lane; i < deg; i += 32)
        mx = fmaxf(mx, logits[(size_t)elist[s + i] * NHD + w]);
#pragma unroll
    for (int o = 16; o; o >>= 1) mx = fmaxf(mx, __shfl_xor_sync(0xffffffffu, mx, o));
    float sum = 0.f;
    for (int i = lane; i < deg; i += 32)
        sum += expf(logits[(size_t)elist[s + i] * NHD + w] - mx);
#pragma unroll
    for (int o = 16; o; o >>= 1) sum += __shfl_xor_sync(0xffffffffu, sum, o);
    if (lane == 0) { s_m[w] = mx; s_d[w] = sum; }
    __syncthreads();

    float m_h = s_m[w];
    float inv_d = 1.0f / s_d[w];

    float acc = 0.f;
    for (int c0 = 0; c0 < deg; c0 += 64) {
        int len = min(64, deg - c0);
        __syncthreads();
        if (tid < len) s_eid[tid] = elist[s + c0 + tid];
        __syncthreads();
        float a0 = 0.f, a1 = 0.f;
        if (lane < len)
            a0 = expf(logits[(size_t)s_eid[lane] * NHD + w] - m_h) * inv_d;
        if (32 + lane < len)
            a1 = expf(logits[(size_t)s_eid[32 + lane] * NHD + w] - m_h) * inv_d;
        for (int i = 0; i < len; i++) {
            float av = (i < 32) ? a0 : a1;
            float att = __shfl_sync(0xffffffffu, av, i & 31);
            acc += att * __ldg(V + (size_t)s_eid[i] * HH + tid);
        }
    }
    agg[(size_t)n * HH + tid] = acc;
}

// ---------------- launch ----------------------------------------------------
extern "C" void kernel_launch(void* const* d_in, const int* in_sizes, int n_in,
                              void* d_out, int out_size)
{
    const float* src_na = (const float*)d_in[0];
    const float* dst_na = (const float*)d_in[1];
    const float* ea     = (const float*)d_in[2];
    const void*  eidx   = d_in[3];
    const float* Wv1 = (const float*)d_in[4];
    const float* bv1 = (const float*)d_in[5];
    const float* Wv2 = (const float*)d_in[6];
    const float* bv2 = (const float*)d_in[7];
    const float* Wv3 = (const float*)d_in[8];
    const float* bv3 = (const float*)d_in[9];
    const float* Wb1 = (const float*)d_in[10];
    const float* bb1 = (const float*)d_in[11];
    const float* Wb2 = (const float*)d_in[12];
    const float* bb2 = (const float*)d_in[13];
    const float* Wb3 = (const float*)d_in[14];
    const float* bb3 = (const float*)d_in[15];
    const float* WO  = (const float*)d_in[16];

    float *pS1, *pT1, *pSv, *pe1, *pe2, *plog, *pagg;
    int *pdeg, *pcur, *poff, *pel, *pdst, *psrc;
    cudaGetSymbolAddress((void**)&pS1, g_S1);
    cudaGetSymbolAddress((void**)&pT1, g_T1);
    cudaGetSymbolAddress((void**)&pSv, g_Sv);
    cudaGetSymbolAddress((void**)&pe1, g_e1);
    cudaGetSymbolAddress((void**)&pe2, g_e2);
    cudaGetSymbolAddress((void**)&plog, g_logits);
    cudaGetSymbolAddress((void**)&pagg, g_agg);
    cudaGetSymbolAddress((void**)&pdeg, g_deg);
    cudaGetSymbolAddress((void**)&pcur, g_cur);
    cudaGetSymbolAddress((void**)&poff, g_off);
    cudaGetSymbolAddress((void**)&pel, g_elist);
    cudaGetSymbolAddress((void**)&pdst, g_dst);
    cudaGetSymbolAddress((void**)&psrc, g_src);

    dim3 gn((NN + 63) / 64, 2);    // 157 x 2
    dim3 ge(EE / 64, 2);           // 5000 x 2

    // 1-2: index normalize
    k_sniff<<<1, 128>>>((const int*)eidx);
    k_convert<<<(EE + 255) / 256, 256>>>(eidx, pdst, psrc);

    // 3-5: node precomputes
    mma_gemm<<<gn, 256, SMEM_GEMM>>>(src_na, 256, Wb1, 768, nullptr,
        nullptr, nullptr, nullptr, nullptr, pS1, NN, 0, nullptr, nullptr);
    mma_gemm<<<gn, 256, SMEM_GEMM>>>(dst_na, 256, Wb1 + 512, 768, nullptr,
        nullptr, nullptr, nullptr, nullptr, pT1, NN, 0, nullptr, nullptr);
    mma_gemm<<<gn, 256, SMEM_GEMM>>>(src_na, 256, Wv1, 512, nullptr,
        nullptr, nullptr, nullptr, nullptr, pSv, NN, 0, nullptr, nullptr);

    // 6: edge h1 = relu(ea@Wb1_e^T + S1[src] + T1[dst] + bb1)  [ncu target]
    mma_gemm<<<ge, 256, SMEM_GEMM>>>(ea, 256, Wb1 + 256, 768, bb1,
        pS1, psrc, pT1, pdst, pe1, EE, 1, nullptr, nullptr);

    // 7-8: logits init, fused h2+logits (h2 never materialized)
    k_initlog<<<(EE * NHD) / 256, 256>>>(bb3, plog);
    mma_gemm<<<ge, 256, SMEM_ACT3>>>(pe1, 256, Wb2, 256, bb2,
        nullptr, nullptr, nullptr, nullptr, nullptr, EE, 3, Wb3, plog);

    // 9: v1 = gelu(ea@Wv1_e^T + Sv[src] + bv1)
    mma_gemm<<<ge, 256, SMEM_GEMM>>>(ea, 256, Wv1 + 256, 512, bv1,
        pSv, psrc, nullptr, nullptr, pe2, EE, 2, nullptr, nullptr);

    // 10-13: CSR build
    k_zero<<<(NN + 255) / 256, 256>>>(pdeg, pcur, NN);
    k_count<<<EE / 256, 256>>>(pdst, pdeg);
    k_scan<<<1, 1024>>>(pdeg, poff);
    k_fill<<<EE / 256, 256>>>(pdst, poff, pcur, pel);

    // 14-15: v2, V
    mma_gemm<<<ge, 256, SMEM_GEMM>>>(pe2, 256, Wv2, 256, bv2,
        nullptr, nullptr, nullptr, nullptr, pe1, EE, 2, nullptr, nullptr);
    mma_gemm<<<ge, 256, SMEM_GEMM>>>(pe1, 256, Wv3, 256, bv3,
        nullptr, nullptr, nullptr, nullptr, pe2, EE, 0, nullptr, nullptr);

    // 16: per-node softmax + aggregation
    k_softmax_agg<<<NN, 256>>>(plog, pe2, poff, pel, pagg);

    // 17: output projection
    mma_gemm<<<gn, 256, SMEM_GEMM>>>(pagg, 256, WO, 256, nullptr,
        nullptr, nullptr, nullptr, nullptr, (float*)d_out, NN, 0,
        nullptr, nullptr);
}

// round 9
// speedup vs baseline: 1.0864x; 1.0864x over previous
#include <cuda_runtime.h>
#include <cuda_bf16.h>
#include <stdint.h>
#include <math.h>

#define NN 10000
#define EE 320000
#define HH 256
#define NHD 8

// weight-pack offsets (floats) in g_Wr
#define WB1_OFF 0
#define WV1_OFF 196608
#define WB2_OFF 327680
#define WV2_OFF 393216
#define WV3_OFF 458752
#define WO_OFF  524288
#define WR_TOT  589824

// ---------------- scratch (static device globals; no runtime alloc) --------
__device__ float g_S1[NN * HH];
__device__ float g_T1[NN * HH];
__device__ float g_Sv[NN * HH];
__device__ float g_e1[(size_t)EE * HH];
__device__ float g_e2[(size_t)EE * HH];
__device__ float g_ear[(size_t)EE * HH];   // tf32-rounded ea
__device__ float g_Sr[NN * HH];            // tf32-rounded src_na
__device__ float g_Tr[NN * HH];            // tf32-rounded dst_na
__device__ float g_Wr[WR_TOT];             // tf32-rounded packed weights
__device__ float g_logits[(size_t)EE * NHD];
__device__ float g_agg[NN * HH];
__device__ int   g_deg[NN];
__device__ int   g_cur[NN];
__device__ int   g_off[NN + 1];
__device__ int   g_elist[EE];
__device__ int   g_dst[EE];
__device__ int   g_src[EE];
__device__ int   g_is64;

__device__ __forceinline__ float gelu_f(float x) {
    return 0.5f * x * (1.0f + erff(x * 0.7071067811865476f));
}

__device__ __forceinline__ unsigned int f2tf32(float f) {
    unsigned int r;
    asm("cvt.rna.tf32.f32 %0, %1;" : "=r"(r) : "f"(f));
    return r;
}
__device__ __forceinline__ float roundtf(float f) {
    return __uint_as_float(f2tf32(f));
}

// m16n8k8 tf32 mma (row.col), fp32 accumulate
__device__ __forceinline__ void mma_tf32(float* c, const unsigned int* a,
                                         const unsigned int* b) {
    asm volatile(
        "mma.sync.aligned.m16n8k8.row.col.f32.tf32.tf32.f32 "
        "{%0,%1,%2,%3}, {%4,%5,%6,%7}, {%8,%9}, {%0,%1,%2,%3};"
        : "+f"(c[0]), "+f"(c[1]), "+f"(c[2]), "+f"(c[3])
        : "r"(a[0]), "r"(a[1]), "r"(a[2]), "r"(a[3]), "r"(b[0]), "r"(b[1]));
}

__device__ __forceinline__ unsigned int smem_u32(const void* p) {
    unsigned int a;
    asm("{ .reg .u64 t; cvta.to.shared.u64 t, %1; cvt.u32.u64 %0, t; }"
        : "=r"(a) : "l"(p));
    return a;
}

// ---------------- tf32 cp.async GEMM: C = act(A @ W^T + bias + gathers) ----
// A, W MUST be tf32-pre-rounded fp32. CTA tile 128x128 (grid.y = 2 halves).
// K=256 in 8 chunks of 32; 3-stage cp.async pipeline (2 chunks in flight).
// act: 0 none, 1 relu, 2 gelu, 3 = relu + fused logits projection (no C)
#define APAD 36
#define STG_FLT (128 * APAD * 2)            // A + B per stage, floats (9216)
#define STG_B   (STG_FLT * 4)               // 36864 bytes
#define SMEM_BYTES (3 * STG_B)              // 110592 bytes

__global__ void __launch_bounds__(256, 2) mma_gemm(
    const float* __restrict__ A, int lda,
    const float* __restrict__ W, int ldw,
    const float* __restrict__ bias,
    const float* __restrict__ add1, const int* __restrict__ idx1,
    const float* __restrict__ add2, const int* __restrict__ idx2,
    float* __restrict__ C, int M, int act, int roundC,
    const float* __restrict__ Wb3, float* __restrict__ logits)
{
    extern __shared__ float smf[];
    const unsigned int smb = smem_u32(smf);

    const int tid = threadIdx.x;
    const int wid = tid >> 5;
    const int lane = tid & 31;
    const int warp_m = wid & 1;
    const int warp_n = wid >> 1;
    const int qr = lane >> 2;
    const int qc = lane & 3;
    const int m0 = blockIdx.x * 128;
    const int n0 = blockIdx.y * 128;

    float c[4][4][4];
#pragma unroll
    for (int i = 0; i < 4; i++)
#pragma unroll
        for (int j = 0; j < 4; j++)
#pragma unroll
            for (int q = 0; q < 4; q++) c[i][j][q] = 0.f;

    const int lr = tid >> 1;            // 0..127 (row)
    const int lf = (tid & 1) * 4;       // 0 or 4 (f4 pair start)

    auto prefetch = [&](int kc, int stg) {
        const unsigned int sA = smb + stg * STG_B;
        const unsigned int sB = sA + 128 * APAD * 4;
        const int kcol = kc * 32;
        // A: 128 rows x 8 f4; thread does rows lr, f4 lf..lf+3 (4 segs)
#pragma unroll
        for (int f = 0; f < 4; f++) {
            int row = lr, f4 = lf + f;
            int mrow = m0 + row;
            int ssz = (mrow < M) ? 16 : 0;
            if (mrow >= M) mrow = M - 1;
            const float* src = A + (size_t)mrow * lda + kcol + f4 * 4;
            unsigned int dst = sA + (row * APAD + f4 * 4) * 4;
            asm volatile("cp.async.cg.shared.global [%0], [%1], 16, %2;"
                         :: "r"(dst), "l"(src), "r"(ssz));
        }
        // B: 128 rows x 8 f4
#pragma unroll
        for (int f = 0; f < 4; f++) {
            int row = lr, f4 = lf + f;
            const float* src = W + (size_t)(n0 + row) * ldw + kcol + f4 * 4;
            unsigned int dst = sB + (row * APAD + f4 * 4) * 4;
            asm volatile("cp.async.cg.shared.global [%0], [%1], 16;"
                         :: "r"(dst), "l"(src));
        }
        asm volatile("cp.async.commit_group;");
    };

    auto compute = [&](int stg) {
        const unsigned int* sA =
            reinterpret_cast<const unsigned int*>(smf) + stg * STG_FLT;
        const unsigned int* sB = sA + 128 * APAD;
#pragma unroll
        for (int ks = 0; ks < 4; ks++) {
            const int k0 = ks * 8;
            unsigned int af[4][4], bf[4][2];
#pragma unroll
            for (int mt = 0; mt < 4; mt++) {
                int base = (warp_m * 64 + mt * 16 + qr) * APAD + k0 + qc;
                af[mt][0] = sA[base];
                af[mt][1] = sA[base + 8 * APAD];
                af[mt][2] = sA[base + 4];
                af[mt][3] = sA[base + 8 * APAD + 4];
            }
#pragma unroll
            for (int nt = 0; nt < 4; nt++) {
                int base = (warp_n * 32 + nt * 8 + qr) * APAD + k0 + qc;
                bf[nt][0] = sB[base];
                bf[nt][1] = sB[base + 4];
            }
#pragma unroll
            for (int mt = 0; mt < 4; mt++)
#pragma unroll
                for (int nt = 0; nt < 4; nt++)
                    mma_tf32(c[mt][nt], af[mt], bf[nt]);
        }
    };

    prefetch(0, 0);
    prefetch(1, 1);

#pragma unroll 1
    for (int kc = 0; kc < 8; kc++) {
        asm volatile("cp.async.wait_group 1;" ::: "memory");
        __syncthreads();
        if (kc + 2 < 8) prefetch(kc + 2, (kc + 2) % 3);
        else asm volatile("cp.async.commit_group;");
        compute(kc % 3);
    }
    __syncthreads();

    // ---- stage accumulators in smem (128 x 132) ----
    float* stage = smf;
#pragma unroll
    for (int mt = 0; mt < 4; mt++) {
#pragma unroll
        for (int nt = 0; nt < 4; nt++) {
            int row = warp_m * 64 + mt * 16 + qr;
            int col = warp_n * 32 + nt * 8 + qc * 2;
            *reinterpret_cast<float2*>(stage + row * 132 + col) =
                make_float2(c[mt][nt][0], c[mt][nt][1]);
            *reinterpret_cast<float2*>(stage + (row + 8) * 132 + col) =
                make_float2(c[mt][nt][2], c[mt][nt][3]);
        }
    }
    __syncthreads();

    if (act == 3) {
        // fused logits: logits[m][h] += sum_n relu(h2_mn) * Wb3[h][n]/sqrt(d)
        float* sW3 = smf + 128 * 132;          // 8 x 128
        float* sb = sW3 + 1024;                // 128
        for (int i = tid; i < 1024; i += 256)
            sW3[i] = Wb3[(i >> 7) * 256 + n0 + (i & 127)];
        if (tid < 128) sb[tid] = bias[n0 + tid];
        __syncthreads();

        int row = tid >> 1, half = tid & 1;
        int m = m0 + row;
        float acc[NHD];
#pragma unroll
        for (int h = 0; h < NHD; h++) acc[h] = 0.f;
        const float* srow = smf + row * 132 + half * 64;
        const float* brow = sb + half * 64;
        const float* wrow = sW3 + half * 64;
#pragma unroll 8
        for (int cc = 0; cc < 64; cc++) {
            float v = fmaxf(srow[cc] + brow[cc], 0.f);
#pragma unroll
            for (int h = 0; h < NHD; h++) acc[h] += v * wrow[h * 128 + cc];
        }
#pragma unroll
        for (int h = 0; h < NHD; h++)
            atomicAdd(&logits[(size_t)m * NHD + h],
                      acc[h] * 0.17677669529663687f);
        return;
    }

    // ---- fused epilogue, float4 coalesced ----
#pragma unroll 4
    for (int i = 0; i < 16; i++) {
        int idx = i * 256 + tid;
        int row = idx >> 5;
        int col = (idx & 31) * 4;
        int m = m0 + row, n = n0 + col;
        if (m < M) {
            float4 v = *reinterpret_cast<float4*>(stage + row * 132 + col);
            if (bias) {
                float4 bv = *reinterpret_cast<const float4*>(bias + n);
                v.x += bv.x; v.y += bv.y; v.z += bv.z; v.w += bv.w;
            }
            if (add1) {
                float4 a = *reinterpret_cast<const float4*>(
                    add1 + (size_t)idx1[m] * 256 + n);
                v.x += a.x; v.y += a.y; v.z += a.z; v.w += a.w;
            }
            if (add2) {
                float4 a = *reinterpret_cast<const float4*>(
                    add2 + (size_t)idx2[m] * 256 + n);
                v.x += a.x; v.y += a.y; v.z += a.z; v.w += a.w;
            }
            if (act == 1) {
                v.x = fmaxf(v.x, 0.f); v.y = fmaxf(v.y, 0.f);
                v.z = fmaxf(v.z, 0.f); v.w = fmaxf(v.w, 0.f);
            } else if (act == 2) {
                v.x = gelu_f(v.x); v.y = gelu_f(v.y);
                v.z = gelu_f(v.z); v.w = gelu_f(v.w);
            }
            if (roundC) {
                v.x = roundtf(v.x); v.y = roundtf(v.y);
                v.z = roundtf(v.z); v.w = roundtf(v.w);
            }
            *reinterpret_cast<float4*>(C + (size_t)m * 256 + n) = v;
        }
    }
}

// ---------------- tf32 pre-round (float4) ----------------------------------
__global__ void k_round(const float* __restrict__ src, float* __restrict__ dst,
                        int n4) {
    int i = blockIdx.x * 256 + threadIdx.x;
    if (i < n4) {
        float4 v = *reinterpret_cast<const float4*>(src + i * 4);
        v.x = roundtf(v.x); v.y = roundtf(v.y);
        v.z = roundtf(v.z); v.w = roundtf(v.w);
        *reinterpret_cast<float4*>(dst + i * 4) = v;
    }
}

// ---------------- logits init: bb3 broadcast * 1/sqrt(d) -------------------
__global__ void k_initlog(const float* __restrict__ bb3,
                          float* __restrict__ logits) {
    int i = blockIdx.x * 256 + threadIdx.x;
    if (i < EE * NHD)
        logits[i] = __ldg(bb3 + (i & 7)) * 0.17677669529663687f;
}

// ---------------- index dtype sniff + normalize ----------------------------
__global__ void k_sniff(const int* __restrict__ buf) {
    __shared__ int nz;
    if (threadIdx.x == 0) nz = 0;
    __syncthreads();
    int w = buf[threadIdx.x * 2 + 1];
    if (w != 0) atomicOr(&nz, 1);
    __syncthreads();
    if (threadIdx.x == 0) g_is64 = nz ? 0 : 1;
}

__global__ void k_convert(const void* __restrict__ buf,
                          int* __restrict__ dst, int* __restrict__ src) {
    int e = blockIdx.x * 256 + threadIdx.x;
    if (e >= EE) return;
    if (g_is64) {
        const long long* p = (const long long*)buf;
        dst[e] = (int)p[e];
        src[e] = (int)p[EE + e];
    } else {
        const int* p = (const int*)buf;
        dst[e] = p[e];
        src[e] = p[EE + e];
    }
}

// ---------------- CSR build -------------------------------------------------
__global__ void k_zero(int* a, int* b, int n) {
    int i = blockIdx.x * blockDim.x + threadIdx.x;
    if (i < n) { a[i] = 0; b[i] = 0; }
}

__global__ void k_count(const int* __restrict__ dst, int* __restrict__ deg) {
    int e = blockIdx.x * 256 + threadIdx.x;
    if (e < EE) atomicAdd(&deg[dst[e]], 1);
}

__global__ void __launch_bounds__(1024) k_scan(
    const int* __restrict__ deg, int* __restrict__ off)
{
    __shared__ int ssum[1024];
    const int t = threadIdx.x;
    const int ITEMS = 10;
    int base = t * ITEMS;
    int loc[ITEMS];
    int s = 0;
#pragma unroll
    for (int i = 0; i < ITEMS; i++) {
        int v = (base + i < NN) ? deg[base + i] : 0;
        loc[i] = s;
        s += v;
    }
    ssum[t] = s;
    __syncthreads();
    for (int d = 1; d < 1024; d <<= 1) {
        int v = (t >= d) ? ssum[t - d] : 0;
        __syncthreads();
        if (t >= d) ssum[t] += v;
        __syncthreads();
    }
    int excl = (t == 0) ? 0 : ssum[t - 1];
#pragma unroll
    for (int i = 0; i < ITEMS; i++)
        if (base + i < NN) off[base + i] = excl + loc[i];
    if (t == 0) off[NN] = ssum[1023];
}

__global__ void k_fill(const int* __restrict__ dst,
                       const int* __restrict__ off, int* __restrict__ cur,
                       int* __restrict__ elist)
{
    int e = blockIdx.x * 256 + threadIdx.x;
    if (e < EE) {
        int d = dst[e];
        int p = off[d] + atomicAdd(&cur[d], 1);
        elist[p] = e;
    }
}

// ---------------- per-node softmax + weighted aggregation ------------------
__global__ void __launch_bounds__(256) k_softmax_agg(
    const float* __restrict__ logits, const float* __restrict__ V,
    const int* __restrict__ off, const int* __restrict__ elist,
    float* __restrict__ agg)
{
    int n = blockIdx.x;
    int tid = threadIdx.x;
    int lane = tid & 31;
    int w = tid >> 5;

    int s = off[n];
    int deg = off[n + 1] - s;
    if (deg == 0) { agg[(size_t)n * HH + tid] = 0.f; return; }

    __shared__ float s_m[NHD], s_d[NHD];
    __shared__ int s_eid[64];

    float mx = -INFINITY;
    for (int i = lane; i < deg; i += 32)
        mx = fmaxf(mx, logits[(size_t)elist[s + i] * NHD + w]);
#pragma unroll
    for (int o = 16; o; o >>= 1) mx = fmaxf(mx, __shfl_xor_sync(0xffffffffu, mx, o));
    float sum = 0.f;
    for (int i = lane; i < deg; i += 32)
        sum += expf(logits[(size_t)elist[s + i] * NHD + w] - mx);
#pragma unroll
    for (int o = 16; o; o >>= 1) sum += __shfl_xor_sync(0xffffffffu, sum, o);
    if (lane == 0) { s_m[w] = mx; s_d[w] = sum; }
    __syncthreads();

    float m_h = s_m[w];
    float inv_d = 1.0f / s_d[w];

    float acc = 0.f;
    for (int c0 = 0; c0 < deg; c0 += 64) {
        int len = min(64, deg - c0);
        __syncthreads();
        if (tid < len) s_eid[tid] = elist[s + c0 + tid];
        __syncthreads();
        float a0 = 0.f, a1 = 0.f;
        if (lane < len)
            a0 = expf(logits[(size_t)s_eid[lane] * NHD + w] - m_h) * inv_d;
        if (32 + lane < len)
            a1 = expf(logits[(size_t)s_eid[32 + lane] * NHD + w] - m_h) * inv_d;
        for (int i = 0; i < len; i++) {
            float av = (i < 32) ? a0 : a1;
            float att = __shfl_sync(0xffffffffu, av, i & 31);
            acc += att * __ldg(V + (size_t)s_eid[i] * HH + tid);
        }
    }
    // round for the final GEMM (consumed via cp.async)
    agg[(size_t)n * HH + tid] = roundtf(acc);
}

// ---------------- launch ----------------------------------------------------
extern "C" void kernel_launch(void* const* d_in, const int* in_sizes, int n_in,
                              void* d_out, int out_size)
{
    const float* src_na = (const float*)d_in[0];
    const float* dst_na = (const float*)d_in[1];
    const float* ea     = (const float*)d_in[2];
    const void*  eidx   = d_in[3];
    const float* Wv1 = (const float*)d_in[4];
    const float* bv1 = (const float*)d_in[5];
    const float* Wv2 = (const float*)d_in[6];
    const float* bv2 = (const float*)d_in[7];
    const float* Wv3 = (const float*)d_in[8];
    const float* bv3 = (const float*)d_in[9];
    const float* Wb1 = (const float*)d_in[10];
    const float* bb1 = (const float*)d_in[11];
    const float* Wb2 = (const float*)d_in[12];
    const float* bb2 = (const float*)d_in[13];
    const float* Wb3 = (const float*)d_in[14];
    const float* bb3 = (const float*)d_in[15];
    const float* WO  = (const float*)d_in[16];

    float *pS1, *pT1, *pSv, *pe1, *pe2, *pear, *pSr, *pTr, *pWr, *plog, *pagg;
    int *pdeg, *pcur, *poff, *pel, *pdst, *psrc;
    cudaGetSymbolAddress((void**)&pS1, g_S1);
    cudaGetSymbolAddress((void**)&pT1, g_T1);
    cudaGetSymbolAddress((void**)&pSv, g_Sv);
    cudaGetSymbolAddress((void**)&pe1, g_e1);
    cudaGetSymbolAddress((void**)&pe2, g_e2);
    cudaGetSymbolAddress((void**)&pear, g_ear);
    cudaGetSymbolAddress((void**)&pSr, g_Sr);
    cudaGetSymbolAddress((void**)&pTr, g_Tr);
    cudaGetSymbolAddress((void**)&pWr, g_Wr);
    cudaGetSymbolAddress((void**)&plog, g_logits);
    cudaGetSymbolAddress((void**)&pagg, g_agg);
    cudaGetSymbolAddress((void**)&pdeg, g_deg);
    cudaGetSymbolAddress((void**)&pcur, g_cur);
    cudaGetSymbolAddress((void**)&poff, g_off);
    cudaGetSymbolAddress((void**)&pel, g_elist);
    cudaGetSymbolAddress((void**)&pdst, g_dst);
    cudaGetSymbolAddress((void**)&psrc, g_src);

    cudaFuncSetAttribute(mma_gemm, cudaFuncAttributeMaxDynamicSharedMemorySize,
                         SMEM_BYTES);

    dim3 gn((NN + 127) / 128, 2);   // 79 x 2
    dim3 ge(EE / 128, 2);           // 2500 x 2

    // index normalize
    k_sniff<<<1, 128>>>((const int*)eidx);
    k_convert<<<(EE + 255) / 256, 256>>>(eidx, pdst, psrc);

    // tf32 pre-round of all GEMM inputs
    k_round<<<(EE * HH / 4 + 255) / 256, 256>>>(ea, pear, EE * HH / 4);
    k_round<<<(NN * HH / 4 + 255) / 256, 256>>>(src_na, pSr, NN * HH / 4);
    k_round<<<(NN * HH / 4 + 255) / 256, 256>>>(dst_na, pTr, NN * HH / 4);
    k_round<<<(196608 / 4 + 255) / 256, 256>>>(Wb1, pWr + WB1_OFF, 196608 / 4);
    k_round<<<(131072 / 4 + 255) / 256, 256>>>(Wv1, pWr + WV1_OFF, 131072 / 4);
    k_round<<<(65536 / 4 + 255) / 256, 256>>>(Wb2, pWr + WB2_OFF, 65536 / 4);
    k_round<<<(65536 / 4 + 255) / 256, 256>>>(Wv2, pWr + WV2_OFF, 65536 / 4);
    k_round<<<(65536 / 4 + 255) / 256, 256>>>(Wv3, pWr + WV3_OFF, 65536 / 4);
    k_round<<<(65536 / 4 + 255) / 256, 256>>>(WO, pWr + WO_OFF, 65536 / 4);

    // node precomputes (outputs consumed as fp32 epilogue adds -> no roundC)
    mma_gemm<<<gn, 256, SMEM_BYTES>>>(pSr, 256, pWr + WB1_OFF, 768, nullptr,
        nullptr, nullptr, nullptr, nullptr, pS1, NN, 0, 0, nullptr, nullptr);
    mma_gemm<<<gn, 256, SMEM_BYTES>>>(pTr, 256, pWr + WB1_OFF + 512, 768, nullptr,
        nullptr, nullptr, nullptr, nullptr, pT1, NN, 0, 0, nullptr, nullptr);
    mma_gemm<<<gn, 256, SMEM_BYTES>>>(pSr, 256, pWr + WV1_OFF, 512, nullptr,
        nullptr, nullptr, nullptr, nullptr, pSv, NN, 0, 0, nullptr, nullptr);

    // h1 = relu(ea@Wb1_e^T + S1[src] + T1[dst] + bb1), rounded for h2 GEMM
    mma_gemm<<<ge, 256, SMEM_BYTES>>>(pear, 256, pWr + WB1_OFF + 256, 768, bb1,
        pS1, psrc, pT1, pdst, pe1, EE, 1, 1, nullptr, nullptr);

    // logits init, fused h2+logits (h2 never materialized)
    k_initlog<<<(EE * NHD) / 256, 256>>>(bb3, plog);
    mma_gemm<<<ge, 256, SMEM_BYTES>>>(pe1, 256, pWr + WB2_OFF, 256, bb2,
        nullptr, nullptr, nullptr, nullptr, nullptr, EE, 3, 0, Wb3, plog);

    // v1 = gelu(ea@Wv1_e^T + Sv[src] + bv1), rounded
    mma_gemm<<<ge, 256, SMEM_BYTES>>>(pear, 256, pWr + WV1_OFF + 256, 512, bv1,
        pSv, psrc, nullptr, nullptr, pe2, EE, 2, 1, nullptr, nullptr);

    // CSR build
    k_zero<<<(NN + 255) / 256, 256>>>(pdeg, pcur, NN);
    k_count<<<EE / 256, 256>>>(pdst, pdeg);
    k_scan<<<1, 1024>>>(pdeg, poff);
    k_fill<<<EE / 256, 256>>>(pdst, poff, pcur, pel);

    // v2 (rounded), V (not rounded -- consumed by fp32 softmax_agg)
    mma_gemm<<<ge, 256, SMEM_BYTES>>>(pe2, 256, pWr + WV2_OFF, 256, bv2,
        nullptr, nullptr, nullptr, nullptr, pe1, EE, 2, 1, nullptr, nullptr);
    mma_gemm<<<ge, 256, SMEM_BYTES>>>(pe1, 256, pWr + WV3_OFF, 256, bv3,
        nullptr, nullptr, nullptr, nullptr, pe2, EE, 0, 0, nullptr, nullptr);

    // per-node softmax + aggregation (agg rounded in-kernel)
    k_softmax_agg<<<NN, 256>>>(plog, pe2, poff, pel, pagg);

    // output projection (no rounding of final output)
    mma_gemm<<<gn, 256, SMEM_BYTES>>>(pagg, 256, pWr + WO_OFF, 256, nullptr,
        nullptr, nullptr, nullptr, nullptr, (float*)d_out, NN, 0, 0,
        nullptr, nullptr);
}

// round 11
// speedup vs baseline: 1.0936x; 1.0067x over previous
#include <cuda_runtime.h>
#include <cuda_bf16.h>
#include <stdint.h>
#include <math.h>

#define NN 10000
#define EE 320000
#define HH 256
#define NHD 8

// packed rounded-weight offsets (floats)
#define WB1_OFF 0
#define WV1_OFF 196608
#define WB2_OFF 327680
#define WV2_OFF 393216
#define WV3_OFF 458752
#define WO_OFF  524288
#define WR_TOT  589824

// ---------------- scratch (static device globals; no runtime alloc) --------
__device__ float g_S1[NN * HH];
__device__ float g_T1[NN * HH];
__device__ float g_Sv[NN * HH];
__device__ float g_e1[(size_t)EE * HH];
__device__ float g_e2[(size_t)EE * HH];
__device__ float g_Wr[WR_TOT];
__device__ float g_logits[(size_t)EE * NHD];
__device__ float g_agg[NN * HH];
__device__ int   g_deg[NN];
__device__ int   g_cur[NN];
__device__ int   g_off[NN + 1];
__device__ int   g_elist[EE];
__device__ int   g_dst[EE];
__device__ int   g_src[EE];
__device__ int   g_is64;

__device__ __forceinline__ float gelu_f(float x) {
    return 0.5f * x * (1.0f + erff(x * 0.7071067811865476f));
}

__device__ __forceinline__ unsigned int f2tf32(float f) {
    unsigned int r;
    asm("cvt.rna.tf32.f32 %0, %1;" : "=r"(r) : "f"(f));
    return r;
}
__device__ __forceinline__ float roundtf(float f) {
    return __uint_as_float(f2tf32(f));
}

// m16n8k8 tf32 mma (row.col), fp32 accumulate
__device__ __forceinline__ void mma_tf32(float* c, const unsigned int* a,
                                         const unsigned int* b) {
    asm volatile(
        "mma.sync.aligned.m16n8k8.row.col.f32.tf32.tf32.f32 "
        "{%0,%1,%2,%3}, {%4,%5,%6,%7}, {%8,%9}, {%0,%1,%2,%3};"
        : "+f"(c[0]), "+f"(c[1]), "+f"(c[2]), "+f"(c[3])
        : "r"(a[0]), "r"(a[1]), "r"(a[2]), "r"(a[3]), "r"(b[0]), "r"(b[1]));
}

// ---------------- tf32 mma.sync GEMM: C = act(A @ W^T + bias + gathers) ----
// A fp32 (rounded in-kernel). W MUST be tf32-pre-rounded (stored verbatim).
// CTA tile 128 x 128 (grid.y = 2 N-halves). K=256, 8 dbl-buffered chunks.
// act: 0 none, 1 relu, 2 gelu, 3 relu + fused logits projection (no C write)
#define APAD 36
#define BUF_FLTS (128 * APAD)         // 4608 floats per buffer
#define SMEM_BYTES (4 * BUF_FLTS * 4) // 73728: A0 A1 B0 B1 (reused as stage)

__global__ void __launch_bounds__(256, 2) mma_gemm(
    const float* __restrict__ A, int lda,
    const float* __restrict__ W, int ldw,
    const float* __restrict__ bias,
    const float* __restrict__ add1, const int* __restrict__ idx1,
    const float* __restrict__ add2, const int* __restrict__ idx2,
    float* __restrict__ C, int M, int act,
    const float* __restrict__ Wb3, float* __restrict__ logits)
{
    extern __shared__ float smf[];
    unsigned int* sm = reinterpret_cast<unsigned int*>(smf);

    const int tid = threadIdx.x;
    const int wid = tid >> 5;
    const int lane = tid & 31;
    const int warp_m = wid & 1;
    const int warp_n = wid >> 1;
    const int qr = lane >> 2;
    const int qc = lane & 3;
    const int m0 = blockIdx.x * 128;
    const int n0 = blockIdx.y * 128;

    float c[4][4][4];
#pragma unroll
    for (int i = 0; i < 4; i++)
#pragma unroll
        for (int j = 0; j < 4; j++)
#pragma unroll
            for (int q = 0; q < 4; q++) c[i][j][q] = 0.f;

    float4 ra[4], rb[4];

    auto load_regs = [&](int kc) {
        const int kcol = kc * 32;
#pragma unroll
        for (int it = 0; it < 4; it++) {
            int idx = tid + it * 256;
            int r = idx >> 3, f4 = idx & 7;
            ra[it] = make_float4(0.f, 0.f, 0.f, 0.f);
            if (m0 + r < M)
                ra[it] = *reinterpret_cast<const float4*>(
                    A + (size_t)(m0 + r) * lda + kcol + f4 * 4);
            rb[it] = *reinterpret_cast<const float4*>(
                W + (size_t)(n0 + r) * ldw + kcol + f4 * 4);
        }
    };
    auto store_regs = [&](int buf) {
        unsigned int* sA = sm + buf * BUF_FLTS;
        float* sBf = smf + (2 + buf) * BUF_FLTS;
#pragma unroll
        for (int it = 0; it < 4; it++) {
            int idx = tid + it * 256;
            int r = idx >> 3, f4 = idx & 7;
            uint4 ta;
            ta.x = f2tf32(ra[it].x); ta.y = f2tf32(ra[it].y);
            ta.z = f2tf32(ra[it].z); ta.w = f2tf32(ra[it].w);
            *reinterpret_cast<uint4*>(sA + r * APAD + f4 * 4) = ta;
            // W is pre-rounded: store bits verbatim (no cvt)
            *reinterpret_cast<float4*>(sBf + r * APAD + f4 * 4) = rb[it];
        }
    };
    auto mma_half = [&](int b, int ks0) {
        const unsigned int* sA = sm + b * BUF_FLTS;
        const unsigned int* sB = sm + (2 + b) * BUF_FLTS;
#pragma unroll
        for (int ks = ks0; ks < ks0 + 2; ks++) {
            const int k0 = ks * 8;
            unsigned int af[4][4], bf[4][2];
#pragma unroll
            for (int mt = 0; mt < 4; mt++) {
                int base = (warp_m * 64 + mt * 16 + qr) * APAD + k0 + qc;
                af[mt][0] = sA[base];
                af[mt][1] = sA[base + 8 * APAD];
                af[mt][2] = sA[base + 4];
                af[mt][3] = sA[base + 8 * APAD + 4];
            }
#pragma unroll
            for (int nt = 0; nt < 4; nt++) {
                int base = (warp_n * 32 + nt * 8 + qr) * APAD + k0 + qc;
                bf[nt][0] = sB[base];
                bf[nt][1] = sB[base + 4];
            }
#pragma unroll
            for (int mt = 0; mt < 4; mt++)
#pragma unroll
                for (int nt = 0; nt < 4; nt++)
                    mma_tf32(c[mt][nt], af[mt], bf[nt]);
        }
    };

    load_regs(0);
    store_regs(0);
    __syncthreads();

#pragma unroll 1
    for (int kc = 0; kc < 8; kc++) {
        const int b = kc & 1;
        if (kc < 7) load_regs(kc + 1);     // LDGs in flight during MMAs
        mma_half(b, 0);
        if (kc < 7) store_regs(b ^ 1);     // cvt+STS after latency covered
        mma_half(b, 2);
        __syncthreads();
    }

    // ---- stage accumulators in smem (128 x 132) ----
    float* stage = smf;
#pragma unroll
    for (int mt = 0; mt < 4; mt++) {
#pragma unroll
        for (int nt = 0; nt < 4; nt++) {
            int row = warp_m * 64 + mt * 16 + qr;
            int col = warp_n * 32 + nt * 8 + qc * 2;
            *reinterpret_cast<float2*>(stage + row * 132 + col) =
                make_float2(c[mt][nt][0], c[mt][nt][1]);
            *reinterpret_cast<float2*>(stage + (row + 8) * 132 + col) =
                make_float2(c[mt][nt][2], c[mt][nt][3]);
        }
    }
    __syncthreads();

    if (act == 3) {
        // fused logits: logits[m][h] += sum_n relu(h2_mn) * Wb3[h][n]/sqrt(d)
        float* sW3 = smf + 128 * 132;          // 8 x 128
        float* sb = sW3 + 1024;                // 128
        for (int i = tid; i < 1024; i += 256)
            sW3[i] = Wb3[(i >> 7) * 256 + n0 + (i & 127)];
        if (tid < 128) sb[tid] = bias[n0 + tid];
        __syncthreads();

        int row = tid >> 1, half = tid & 1;
        int m = m0 + row;
        float acc[NHD];
#pragma unroll
        for (int h = 0; h < NHD; h++) acc[h] = 0.f;
        const float* srow = smf + row * 132 + half * 64;
        const float* brow = sb + half * 64;
        const float* wrow = sW3 + half * 64;
#pragma unroll 8
        for (int cc = 0; cc < 64; cc++) {
            float v = fmaxf(srow[cc] + brow[cc], 0.f);
#pragma unroll
            for (int h = 0; h < NHD; h++) acc[h] += v * wrow[h * 128 + cc];
        }
#pragma unroll
        for (int h = 0; h < NHD; h++)
            atomicAdd(&logits[(size_t)m * NHD + h],
                      acc[h] * 0.17677669529663687f);
        return;
    }

    // ---- fused epilogue, float4 coalesced ----
#pragma unroll 4
    for (int i = 0; i < 16; i++) {
        int idx = i * 256 + tid;
        int row = idx >> 5;
        int col = (idx & 31) * 4;
        int m = m0 + row, n = n0 + col;
        if (m < M) {
            float4 v = *reinterpret_cast<float4*>(stage + row * 132 + col);
            if (bias) {
                float4 bv = *reinterpret_cast<const float4*>(bias + n);
                v.x += bv.x; v.y += bv.y; v.z += bv.z; v.w += bv.w;
            }
            if (add1) {
                float4 a = *reinterpret_cast<const float4*>(
                    add1 + (size_t)idx1[m] * 256 + n);
                v.x += a.x; v.y += a.y; v.z += a.z; v.w += a.w;
            }
            if (add2) {
                float4 a = *reinterpret_cast<const float4*>(
                    add2 + (size_t)idx2[m] * 256 + n);
                v.x += a.x; v.y += a.y; v.z += a.z; v.w += a.w;
            }
            if (act == 1) {
                v.x = fmaxf(v.x, 0.f); v.y = fmaxf(v.y, 0.f);
                v.z = fmaxf(v.z, 0.f); v.w = fmaxf(v.w, 0.f);
            } else if (act == 2) {
                v.x = gelu_f(v.x); v.y = gelu_f(v.y);
                v.z = gelu_f(v.z); v.w = gelu_f(v.w);
            }
            *reinterpret_cast<float4*>(C + (size_t)m * 256 + n) = v;
        }
    }
}

// ---------------- weight pre-round into packed buffer ----------------------
__global__ void k_roundW(const float* __restrict__ Wb1,
                         const float* __restrict__ Wv1,
                         const float* __restrict__ Wb2,
                         const float* __restrict__ Wv2,
                         const float* __restrict__ Wv3,
                         const float* __restrict__ WO,
                         float* __restrict__ Wr) {
    int i4 = blockIdx.x * 256 + threadIdx.x;
    if (i4 >= WR_TOT / 4) return;
    int f = i4 * 4;
    const float* src; int off;
    if (f < WV1_OFF)      { src = Wb1; off = WB1_OFF; }
    else if (f < WB2_OFF) { src = Wv1; off = WV1_OFF; }
    else if (f < WV2_OFF) { src = Wb2; off = WB2_OFF; }
    else if (f < WV3_OFF) { src = Wv2; off = WV2_OFF; }
    else if (f < WO_OFF)  { src = Wv3; off = WV3_OFF; }
    else                  { src = WO;  off = WO_OFF; }
    float4 v = *reinterpret_cast<const float4*>(src + (f - off));
    v.x = roundtf(v.x); v.y = roundtf(v.y);
    v.z = roundtf(v.z); v.w = roundtf(v.w);
    *reinterpret_cast<float4*>(Wr + f) = v;
}

// ---------------- logits init: bb3 broadcast * 1/sqrt(d) -------------------
__global__ void k_initlog(const float* __restrict__ bb3,
                          float* __restrict__ logits) {
    int i = blockIdx.x * 256 + threadIdx.x;
    if (i < EE * NHD)
        logits[i] = __ldg(bb3 + (i & 7)) * 0.17677669529663687f;
}

// ---------------- index dtype sniff + normalize ----------------------------
__global__ void k_sniff(const int* __restrict__ buf) {
    __shared__ int nz;
    if (threadIdx.x == 0) nz = 0;
    __syncthreads();
    int w = buf[threadIdx.x * 2 + 1];
    if (w != 0) atomicOr(&nz, 1);
    __syncthreads();
    if (threadIdx.x == 0) g_is64 = nz ? 0 : 1;
}

__global__ void k_convert(const void* __restrict__ buf,
                          int* __restrict__ dst, int* __restrict__ src) {
    int e = blockIdx.x * 256 + threadIdx.x;
    if (e >= EE) return;
    if (g_is64) {
        const long long* p = (const long long*)buf;
        dst[e] = (int)p[e];
        src[e] = (int)p[EE + e];
    } else {
        const int* p = (const int*)buf;
        dst[e] = p[e];
        src[e] = p[EE + e];
    }
}

// ---------------- CSR build -------------------------------------------------
__global__ void k_zero(int* a, int* b, int n) {
    int i = blockIdx.x * blockDim.x + threadIdx.x;
    if (i < n) { a[i] = 0; b[i] = 0; }
}

__global__ void k_count(const int* __restrict__ dst, int* __restrict__ deg) {
    int e = blockIdx.x * 256 + threadIdx.x;
    if (e < EE) atomicAdd(&deg[dst[e]], 1);
}

__global__ void __launch_bounds__(1024) k_scan(
    const int* __restrict__ deg, int* __restrict__ off)
{
    __shared__ int ssum[1024];
    const int t = threadIdx.x;
    const int ITEMS = 10;
    int base = t * ITEMS;
    int loc[ITEMS];
    int s = 0;
#pragma unroll
    for (int i = 0; i < ITEMS; i++) {
        int v = (base + i < NN) ? deg[base + i] : 0;
        loc[i] = s;
        s += v;
    }
    ssum[t] = s;
    __syncthreads();
    for (int d = 1; d < 1024; d <<= 1) {
        int v = (t >= d) ? ssum[t - d] : 0;
        __syncthreads();
        if (t >= d) ssum[t] += v;
        __syncthreads();
    }
    int excl = (t == 0) ? 0 : ssum[t - 1];
#pragma unroll
    for (int i = 0; i < ITEMS; i++)
        if (base + i < NN) off[base + i] = excl + loc[i];
    if (t == 0) off[NN] = ssum[1023];
}

__global__ void k_fill(const int* __restrict__ dst,
                       const int* __restrict__ off, int* __restrict__ cur,
                       int* __restrict__ elist)
{
    int e = blockIdx.x * 256 + threadIdx.x;
    if (e < EE) {
        int d = dst[e];
        int p = off[d] + atomicAdd(&cur[d], 1);
        elist[p] = e;
    }
}

// ---------------- per-node softmax + weighted aggregation ------------------
__global__ void __launch_bounds__(256) k_softmax_agg(
    const float* __restrict__ logits, const float* __restrict__ V,
    const int* __restrict__ off, const int* __restrict__ elist,
    float* __restrict__ agg)
{
    int n = blockIdx.x;
    int tid = threadIdx.x;
    int lane = tid & 31;
    int w = tid >> 5;

    int s = off[n];
    int deg = off[n + 1] - s;
    if (deg == 0) { agg[(size_t)n * HH + tid] = 0.f; return; }

    __shared__ float s_m[NHD], s_d[NHD];
    __shared__ int s_eid[64];

    float mx = -INFINITY;
    for (int i = lane; i < deg; i += 32)
        mx = fmaxf(mx, logits[(size_t)elist[s + i] * NHD + w]);
#pragma unroll
    for (int o = 16; o; o >>= 1) mx = fmaxf(mx, __shfl_xor_sync(0xffffffffu, mx, o));
    float sum = 0.f;
    for (int i = lane; i < deg; i += 32)
        sum += expf(logits[(size_t)elist[s + i] * NHD + w] - mx);
#pragma unroll
    for (int o = 16; o; o >>= 1) sum += __shfl_xor_sync(0xffffffffu, sum, o);
    if (lane == 0) { s_m[w] = mx; s_d[w] = sum; }
    __syncthreads();

    float m_h = s_m[w];
    float inv_d = 1.0f / s_d[w];

    float acc = 0.f;
    for (int c0 = 0; c0 < deg; c0 += 64) {
        int len = min(64, deg - c0);
        __syncthreads();
        if (tid < len) s_eid[tid] = elist[s + c0 + tid];
        __syncthreads();
        float a0 = 0.f, a1 = 0.f;
        if (lane < len)
            a0 = expf(logits[(size_t)s_eid[lane] * NHD + w] - m_h) * inv_d;
        if (32 + lane < len)
            a1 = expf(logits[(size_t)s_eid[32 + lane] * NHD + w] - m_h) * inv_d;
        for (int i = 0; i < len; i++) {
            float av = (i < 32) ? a0 : a1;
            float att = __shfl_sync(0xffffffffu, av, i & 31);
            acc += att * __ldg(V + (size_t)s_eid[i] * HH + tid);
        }
    }
    agg[(size_t)n * HH + tid] = acc;
}

// ---------------- launch ----------------------------------------------------
extern "C" void kernel_launch(void* const* d_in, const int* in_sizes, int n_in,
                              void* d_out, int out_size)
{
    const float* src_na = (const float*)d_in[0];
    const float* dst_na = (const float*)d_in[1];
    const float* ea     = (const float*)d_in[2];
    const void*  eidx   = d_in[3];
    const float* Wv1 = (const float*)d_in[4];
    const float* bv1 = (const float*)d_in[5];
    const float* Wv2 = (const float*)d_in[6];
    const float* bv2 = (const float*)d_in[7];
    const float* Wv3 = (const float*)d_in[8];
    const float* bv3 = (const float*)d_in[9];
    const float* Wb1 = (const float*)d_in[10];
    const float* bb1 = (const float*)d_in[11];
    const float* Wb2 = (const float*)d_in[12];
    const float* bb2 = (const float*)d_in[13];
    const float* Wb3 = (const float*)d_in[14];
    const float* bb3 = (const float*)d_in[15];
    const float* WO  = (const float*)d_in[16];

    float *pS1, *pT1, *pSv, *pe1, *pe2, *pWr, *plog, *pagg;
    int *pdeg, *pcur, *poff, *pel, *pdst, *psrc;
    cudaGetSymbolAddress((void**)&pS1, g_S1);
    cudaGetSymbolAddress((void**)&pT1, g_T1);
    cudaGetSymbolAddress((void**)&pSv, g_Sv);
    cudaGetSymbolAddress((void**)&pe1, g_e1);
    cudaGetSymbolAddress((void**)&pe2, g_e2);
    cudaGetSymbolAddress((void**)&pWr, g_Wr);
    cudaGetSymbolAddress((void**)&plog, g_logits);
    cudaGetSymbolAddress((void**)&pagg, g_agg);
    cudaGetSymbolAddress((void**)&pdeg, g_deg);
    cudaGetSymbolAddress((void**)&pcur, g_cur);
    cudaGetSymbolAddress((void**)&poff, g_off);
    cudaGetSymbolAddress((void**)&pel, g_elist);
    cudaGetSymbolAddress((void**)&pdst, g_dst);
    cudaGetSymbolAddress((void**)&psrc, g_src);

    cudaFuncSetAttribute(mma_gemm, cudaFuncAttributeMaxDynamicSharedMemorySize,
                         SMEM_BYTES);

    dim3 gn((NN + 127) / 128, 2);   // 79 x 2
    dim3 ge(EE / 128, 2);           // 2500 x 2

    // 1-3: index normalize + weight pre-round
    k_sniff<<<1, 128>>>((const int*)eidx);
    k_convert<<<(EE + 255) / 256, 256>>>(eidx, pdst, psrc);
    k_roundW<<<(WR_TOT / 4 + 255) / 256, 256>>>(Wb1, Wv1, Wb2, Wv2, Wv3, WO, pWr);

    // 4: Sv node precompute; 5: v1 EDGE GEMM (ncu profiled slot)
    mma_gemm<<<gn, 256, SMEM_BYTES>>>(src_na, 256, pWr + WV1_OFF, 512, nullptr,
        nullptr, nullptr, nullptr, nullptr, pSv, NN, 0, nullptr, nullptr);
    mma_gemm<<<ge, 256, SMEM_BYTES>>>(ea, 256, pWr + WV1_OFF + 256, 512, bv1,
        pSv, psrc, nullptr, nullptr, pe2, EE, 2, nullptr, nullptr);   // v1 gelu

    // 6-7: remaining node precomputes
    mma_gemm<<<gn, 256, SMEM_BYTES>>>(src_na, 256, pWr + WB1_OFF, 768, nullptr,
        nullptr, nullptr, nullptr, nullptr, pS1, NN, 0, nullptr, nullptr);
    mma_gemm<<<gn, 256, SMEM_BYTES>>>(dst_na, 256, pWr + WB1_OFF + 512, 768, nullptr,
        nullptr, nullptr, nullptr, nullptr, pT1, NN, 0, nullptr, nullptr);

    // 8: h1 = relu(ea@Wb1_e^T + S1[src] + T1[dst] + bb1)
    mma_gemm<<<ge, 256, SMEM_BYTES>>>(ea, 256, pWr + WB1_OFF + 256, 768, bb1,
        pS1, psrc, pT1, pdst, pe1, EE, 1, nullptr, nullptr);

    // 9-10: logits init + fused h2+logits (h2 never materialized)
    k_initlog<<<(EE * NHD) / 256, 256>>>(bb3, plog);
    mma_gemm<<<ge, 256, SMEM_BYTES>>>(pe1, 256, pWr + WB2_OFF, 256, bb2,
        nullptr, nullptr, nullptr, nullptr, nullptr, EE, 3, Wb3, plog);

    // 11-14: CSR build
    k_zero<<<(NN + 255) / 256, 256>>>(pdeg, pcur, NN);
    k_count<<<EE / 256, 256>>>(pdst, pdeg);
    k_scan<<<1, 1024>>>(pdeg, poff);
    k_fill<<<EE / 256, 256>>>(pdst, poff, pcur, pel);

    // 15-16: v2, V
    mma_gemm<<<ge, 256, SMEM_BYTES>>>(pe2, 256, pWr + WV2_OFF, 256, bv2,
        nullptr, nullptr, nullptr, nullptr, pe1, EE, 2, nullptr, nullptr);
    mma_gemm<<<ge, 256, SMEM_BYTES>>>(pe1, 256, pWr + WV3_OFF, 256, bv3,
        nullptr, nullptr, nullptr, nullptr, pe2, EE, 0, nullptr, nullptr);

    // 17: per-node softmax + aggregation
    k_softmax_agg<<<NN, 256>>>(plog, pe2, poff, pel, pagg);

    // 18: output projection
    mma_gemm<<<gn, 256, SMEM_BYTES>>>(pagg, 256, pWr + WO_OFF, 256, nullptr,
        nullptr, nullptr, nullptr, nullptr, (float*)d_out, NN, 0,
        nullptr, nullptr);
}

// round 12
// speedup vs baseline: 1.3396x; 1.2249x over previous
#include <cuda_runtime.h>
#include <cuda_bf16.h>
#include <stdint.h>
#include <math.h>

#define NN 10000
#define EE 320000
#define HH 256
#define NHD 8

// ---------------- scratch (static device globals; no runtime alloc) --------
__device__ float g_S1[NN * HH];
__device__ float g_T1[NN * HH];
__device__ float g_Sv[NN * HH];
__device__ float g_e1[(size_t)EE * HH];
__device__ float g_e2[(size_t)EE * HH];
__device__ float g_logits[(size_t)EE * NHD];
__device__ float g_agg[NN * HH];
__device__ int   g_deg[NN];
__device__ int   g_cur[NN];
__device__ int   g_off[NN + 1];
__device__ int   g_elist[EE];
__device__ int   g_dst[EE];
__device__ int   g_src[EE];
__device__ int   g_is64;

__device__ __forceinline__ float gelu_f(float x) {
    return 0.5f * x * (1.0f + erff(x * 0.7071067811865476f));
}

__device__ __forceinline__ unsigned int f2tf32(float f) {
    unsigned int r;
    asm("cvt.rna.tf32.f32 %0, %1;" : "=r"(r) : "f"(f));
    return r;
}

// m16n8k8 tf32 mma (row.col), fp32 accumulate
__device__ __forceinline__ void mma_tf32(float* c, const unsigned int* a,
                                         const unsigned int* b) {
    asm volatile(
        "mma.sync.aligned.m16n8k8.row.col.f32.tf32.tf32.f32 "
        "{%0,%1,%2,%3}, {%4,%5,%6,%7}, {%8,%9}, {%0,%1,%2,%3};"
        : "+f"(c[0]), "+f"(c[1]), "+f"(c[2]), "+f"(c[3])
        : "r"(a[0]), "r"(a[1]), "r"(a[2]), "r"(a[3]), "r"(b[0]), "r"(b[1]));
}

__device__ __forceinline__ unsigned int smem_u32(const void* p) {
    unsigned int a;
    asm("{ .reg .u64 t; cvta.to.shared.u64 t, %1; cvt.u32.u64 %0, t; }"
        : "=r"(a) : "l"(p));
    return a;
}

// ldmatrix on b32 data: m8n8.b16 matrix = 8 rows x 4 b32 cols; lane j gets
// element [j>>2][j&3] -- exactly the tf32 fragment layout.
__device__ __forceinline__ void ldsm_x4(unsigned int* r, unsigned int addr) {
    asm volatile(
        "ldmatrix.sync.aligned.m8n8.x4.shared.b16 {%0,%1,%2,%3}, [%4];"
        : "=r"(r[0]), "=r"(r[1]), "=r"(r[2]), "=r"(r[3]) : "r"(addr));
}
__device__ __forceinline__ void ldsm_x2(unsigned int* r, unsigned int addr) {
    asm volatile(
        "ldmatrix.sync.aligned.m8n8.x2.shared.b16 {%0,%1}, [%2];"
        : "=r"(r[0]), "=r"(r[1]) : "r"(addr));
}

// ---------------- tf32 mma.sync GEMM: C = act(A @ W^T + bias + gathers) ----
// CTA tile 128 x 128 (grid.y over 2 N-halves). K=256, 8 dbl-buffered chunks.
// act: 0 none, 1 relu, 2 gelu, 3 relu + fused logits projection (no C write)
#define APAD 36
#define BUF_FLTS (128 * APAD)         // 4608 floats per buffer
#define SMEM_BYTES (4 * BUF_FLTS * 4) // 73728: A0 A1 B0 B1 (reused as stage)

__global__ void __launch_bounds__(256, 2) mma_gemm(
    const float* __restrict__ A, int lda,
    const float* __restrict__ W, int ldw,
    const float* __restrict__ bias,
    const float* __restrict__ add1, const int* __restrict__ idx1,
    const float* __restrict__ add2, const int* __restrict__ idx2,
    float* __restrict__ C, int M, int act,
    const float* __restrict__ Wb3, float* __restrict__ logits)
{
    extern __shared__ float smf[];
    unsigned int* sm = reinterpret_cast<unsigned int*>(smf);
    const unsigned int smb = smem_u32(smf);

    const int tid = threadIdx.x;
    const int wid = tid >> 5;
    const int lane = tid & 31;
    const int warp_m = wid & 1;
    const int warp_n = wid >> 1;
    const int qr = lane >> 2;
    const int qc = lane & 3;
    const int m0 = blockIdx.x * 128;
    const int n0 = blockIdx.y * 128;

    // ldmatrix per-lane row-address constants (float offsets)
    const int lm = lane >> 3;             // matrix index 0..3
    const int lr8 = lane & 7;             // row within matrix
    const int a_lane = (warp_m * 64 + ((lm & 1) << 3) + lr8) * APAD
                     + ((lm >> 1) << 2);
    const int blm = (lane & 15) >> 3;     // B matrix index 0..1 (lanes 0-15)
    const int b_lane = (warp_n * 32 + lr8) * APAD + (blm << 2);

    float c[4][4][4];
#pragma unroll
    for (int i = 0; i < 4; i++)
#pragma unroll
        for (int j = 0; j < 4; j++)
#pragma unroll
            for (int q = 0; q < 4; q++) c[i][j][q] = 0.f;

    float4 ra[4], rb[4];

    auto load_regs = [&](int kc) {
        const int kcol = kc * 32;
#pragma unroll
        for (int it = 0; it < 4; it++) {
            int idx = tid + it * 256;
            int r = idx >> 3, f4 = idx & 7;
            ra[it] = make_float4(0.f, 0.f, 0.f, 0.f);
            if (m0 + r < M)
                ra[it] = *reinterpret_cast<const float4*>(
                    A + (size_t)(m0 + r) * lda + kcol + f4 * 4);
            rb[it] = *reinterpret_cast<const float4*>(
                W + (size_t)(n0 + r) * ldw + kcol + f4 * 4);
        }
    };
    auto store_regs = [&](int buf) {
        unsigned int* sA = sm + buf * BUF_FLTS;
        unsigned int* sB = sm + (2 + buf) * BUF_FLTS;
#pragma unroll
        for (int it = 0; it < 4; it++) {
            int idx = tid + it * 256;
            int r = idx >> 3, f4 = idx & 7;
            uint4 ta, tb;
            ta.x = f2tf32(ra[it].x); ta.y = f2tf32(ra[it].y);
            ta.z = f2tf32(ra[it].z); ta.w = f2tf32(ra[it].w);
            tb.x = f2tf32(rb[it].x); tb.y = f2tf32(rb[it].y);
            tb.z = f2tf32(rb[it].z); tb.w = f2tf32(rb[it].w);
            *reinterpret_cast<uint4*>(sA + r * APAD + f4 * 4) = ta;
            *reinterpret_cast<uint4*>(sB + r * APAD + f4 * 4) = tb;
        }
    };
    auto mma_half = [&](int b, int ks0) {
        const unsigned int baseA = smb + (b * BUF_FLTS) * 4;
        const unsigned int baseB = smb + ((2 + b) * BUF_FLTS) * 4;
#pragma unroll
        for (int ks = ks0; ks < ks0 + 2; ks++) {
            unsigned int af[4][4], bf[4][2];
#pragma unroll
            for (int mt = 0; mt < 4; mt++)
                ldsm_x4(af[mt],
                        baseA + (unsigned)(a_lane + mt * 16 * APAD + ks * 8) * 4);
#pragma unroll
            for (int nt = 0; nt < 4; nt++)
                ldsm_x2(bf[nt],
                        baseB + (unsigned)(b_lane + nt * 8 * APAD + ks * 8) * 4);
#pragma unroll
            for (int mt = 0; mt < 4; mt++)
#pragma unroll
                for (int nt = 0; nt < 4; nt++)
                    mma_tf32(c[mt][nt], af[mt], bf[nt]);
        }
    };

    load_regs(0);
    store_regs(0);
    __syncthreads();

#pragma unroll 1
    for (int kc = 0; kc < 8; kc++) {
        const int b = kc & 1;
        if (kc < 7) load_regs(kc + 1);     // LDGs in flight during MMAs
        mma_half(b, 0);
        if (kc < 7) store_regs(b ^ 1);     // cvt+STS after latency covered
        mma_half(b, 2);
        __syncthreads();
    }

    // ---- stage accumulators in smem (128 x 132) ----
    float* stage = smf;
#pragma unroll
    for (int mt = 0; mt < 4; mt++) {
#pragma unroll
        for (int nt = 0; nt < 4; nt++) {
            int row = warp_m * 64 + mt * 16 + qr;
            int col = warp_n * 32 + nt * 8 + qc * 2;
            *reinterpret_cast<float2*>(stage + row * 132 + col) =
                make_float2(c[mt][nt][0], c[mt][nt][1]);
            *reinterpret_cast<float2*>(stage + (row + 8) * 132 + col) =
                make_float2(c[mt][nt][2], c[mt][nt][3]);
        }
    }
    __syncthreads();

    if (act == 3) {
        // fused logits: logits[m][h] += sum_n relu(h2_mn) * Wb3[h][n]/sqrt(d)
        float* sW3 = smf + 128 * 132;          // 8 x 128
        float* sb = sW3 + 1024;                // 128
        for (int i = tid; i < 1024; i += 256)
            sW3[i] = Wb3[(i >> 7) * 256 + n0 + (i & 127)];
        if (tid < 128) sb[tid] = bias[n0 + tid];
        __syncthreads();

        int row = tid >> 1, half = tid & 1;
        int m = m0 + row;
        float acc[NHD];
#pragma unroll
        for (int h = 0; h < NHD; h++) acc[h] = 0.f;
        const float* srow = smf + row * 132 + half * 64;
        const float* brow = sb + half * 64;
        const float* wrow = sW3 + half * 64;
#pragma unroll 8
        for (int cc = 0; cc < 64; cc++) {
            float v = fmaxf(srow[cc] + brow[cc], 0.f);
#pragma unroll
            for (int h = 0; h < NHD; h++) acc[h] += v * wrow[h * 128 + cc];
        }
#pragma unroll
        for (int h = 0; h < NHD; h++)
            atomicAdd(&logits[(size_t)m * NHD + h],
                      acc[h] * 0.17677669529663687f);
        return;
    }

    // ---- fused epilogue, float4 coalesced ----
#pragma unroll 4
    for (int i = 0; i < 16; i++) {
        int idx = i * 256 + tid;
        int row = idx >> 5;
        int col = (idx & 31) * 4;
        int m = m0 + row, n = n0 + col;
        if (m < M) {
            float4 v = *reinterpret_cast<float4*>(stage + row * 132 + col);
            if (bias) {
                float4 bv = *reinterpret_cast<const float4*>(bias + n);
                v.x += bv.x; v.y += bv.y; v.z += bv.z; v.w += bv.w;
            }
            if (add1) {
                float4 a = *reinterpret_cast<const float4*>(
                    add1 + (size_t)idx1[m] * 256 + n);
                v.x += a.x; v.y += a.y; v.z += a.z; v.w += a.w;
            }
            if (add2) {
                float4 a = *reinterpret_cast<const float4*>(
                    add2 + (size_t)idx2[m] * 256 + n);
                v.x += a.x; v.y += a.y; v.z += a.z; v.w += a.w;
            }
            if (act == 1) {
                v.x = fmaxf(v.x, 0.f); v.y = fmaxf(v.y, 0.f);
                v.z = fmaxf(v.z, 0.f); v.w = fmaxf(v.w, 0.f);
            } else if (act == 2) {
                v.x = gelu_f(v.x); v.y = gelu_f(v.y);
                v.z = gelu_f(v.z); v.w = gelu_f(v.w);
            }
            *reinterpret_cast<float4*>(C + (size_t)m * 256 + n) = v;
        }
    }
}

// ---------------- logits init: bb3 broadcast * 1/sqrt(d) -------------------
__global__ void k_initlog(const float* __restrict__ bb3,
                          float* __restrict__ logits) {
    int i = blockIdx.x * 256 + threadIdx.x;
    if (i < EE * NHD)
        logits[i] = __ldg(bb3 + (i & 7)) * 0.17677669529663687f;
}

// ---------------- index dtype sniff + normalize ----------------------------
__global__ void k_sniff(const int* __restrict__ buf) {
    __shared__ int nz;
    if (threadIdx.x == 0) nz = 0;
    __syncthreads();
    int w = buf[threadIdx.x * 2 + 1];
    if (w != 0) atomicOr(&nz, 1);
    __syncthreads();
    if (threadIdx.x == 0) g_is64 = nz ? 0 : 1;
}

__global__ void k_convert(const void* __restrict__ buf,
                          int* __restrict__ dst, int* __restrict__ src) {
    int e = blockIdx.x * 256 + threadIdx.x;
    if (e >= EE) return;
    if (g_is64) {
        const long long* p = (const long long*)buf;
        dst[e] = (int)p[e];
        src[e] = (int)p[EE + e];
    } else {
        const int* p = (const int*)buf;
        dst[e] = p[e];
        src[e] = p[EE + e];
    }
}

// ---------------- CSR build -------------------------------------------------
__global__ void k_zero(int* a, int* b, int n) {
    int i = blockIdx.x * blockDim.x + threadIdx.x;
    if (i < n) { a[i] = 0; b[i] = 0; }
}

__global__ void k_count(const int* __restrict__ dst, int* __restrict__ deg) {
    int e = blockIdx.x * 256 + threadIdx.x;
    if (e < EE) atomicAdd(&deg[dst[e]], 1);
}

__global__ void __launch_bounds__(1024) k_scan(
    const int* __restrict__ deg, int* __restrict__ off)
{
    __shared__ int ssum[1024];
    const int t = threadIdx.x;
    const int ITEMS = 10;
    int base = t * ITEMS;
    int loc[ITEMS];
    int s = 0;
#pragma unroll
    for (int i = 0; i < ITEMS; i++) {
        int v = (base + i < NN) ? deg[base + i] : 0;
        loc[i] = s;
        s += v;
    }
    ssum[t] = s;
    __syncthreads();
    for (int d = 1; d < 1024; d <<= 1) {
        int v = (t >= d) ? ssum[t - d] : 0;
        __syncthreads();
        if (t >= d) ssum[t] += v;
        __syncthreads();
    }
    int excl = (t == 0) ? 0 : ssum[t - 1];
#pragma unroll
    for (int i = 0; i < ITEMS; i++)
        if (base + i < NN) off[base + i] = excl + loc[i];
    if (t == 0) off[NN] = ssum[1023];
}

__global__ void k_fill(const int* __restrict__ dst,
                       const int* __restrict__ off, int* __restrict__ cur,
                       int* __restrict__ elist)
{
    int e = blockIdx.x * 256 + threadIdx.x;
    if (e < EE) {
        int d = dst[e];
        int p = off[d] + atomicAdd(&cur[d], 1);
        elist[p] = e;
    }
}

// ---------------- per-node softmax + weighted aggregation ------------------
__global__ void __launch_bounds__(256) k_softmax_agg(
    const float* __restrict__ logits, const float* __restrict__ V,
    const int* __restrict__ off, const int* __restrict__ elist,
    float* __restrict__ agg)
{
    int n = blockIdx.x;
    int tid = threadIdx.x;
    int lane = tid & 31;
    int w = tid >> 5;

    int s = off[n];
    int deg = off[n + 1] - s;
    if (deg == 0) { agg[(size_t)n * HH + tid] = 0.f; return; }

    __shared__ float s_m[NHD], s_d[NHD];
    __shared__ int s_eid[64];

    float mx = -INFINITY;
    for (int i = lane; i < deg; i += 32)
        mx = fmaxf(mx, logits[(size_t)elist[s + i] * NHD + w]);
#pragma unroll
    for (int o = 16; o; o >>= 1) mx = fmaxf(mx, __shfl_xor_sync(0xffffffffu, mx, o));
    float sum = 0.f;
    for (int i = lane; i < deg; i += 32)
        sum += expf(logits[(size_t)elist[s + i] * NHD + w] - mx);
#pragma unroll
    for (int o = 16; o; o >>= 1) sum += __shfl_xor_sync(0xffffffffu, sum, o);
    if (lane == 0) { s_m[w] = mx; s_d[w] = sum; }
    __syncthreads();

    float m_h = s_m[w];
    float inv_d = 1.0f / s_d[w];

    float acc = 0.f;
    for (int c0 = 0; c0 < deg; c0 += 64) {
        int len = min(64, deg - c0);
        __syncthreads();
        if (tid < len) s_eid[tid] = elist[s + c0 + tid];
        __syncthreads();
        float a0 = 0.f, a1 = 0.f;
        if (lane < len)
            a0 = expf(logits[(size_t)s_eid[lane] * NHD + w] - m_h) * inv_d;
        if (32 + lane < len)
            a1 = expf(logits[(size_t)s_eid[32 + lane] * NHD + w] - m_h) * inv_d;
        for (int i = 0; i < len; i++) {
            float av = (i < 32) ? a0 : a1;
            float att = __shfl_sync(0xffffffffu, av, i & 31);
            acc += att * __ldg(V + (size_t)s_eid[i] * HH + tid);
        }
    }
    agg[(size_t)n * HH + tid] = acc;
}

// ---------------- launch ----------------------------------------------------
extern "C" void kernel_launch(void* const* d_in, const int* in_sizes, int n_in,
                              void* d_out, int out_size)
{
    const float* src_na = (const float*)d_in[0];
    const float* dst_na = (const float*)d_in[1];
    const float* ea     = (const float*)d_in[2];
    const void*  eidx   = d_in[3];
    const float* Wv1 = (const float*)d_in[4];
    const float* bv1 = (const float*)d_in[5];
    const float* Wv2 = (const float*)d_in[6];
    const float* bv2 = (const float*)d_in[7];
    const float* Wv3 = (const float*)d_in[8];
    const float* bv3 = (const float*)d_in[9];
    const float* Wb1 = (const float*)d_in[10];
    const float* bb1 = (const float*)d_in[11];
    const float* Wb2 = (const float*)d_in[12];
    const float* bb2 = (const float*)d_in[13];
    const float* Wb3 = (const float*)d_in[14];
    const float* bb3 = (const float*)d_in[15];
    const float* WO  = (const float*)d_in[16];

    float *pS1, *pT1, *pSv, *pe1, *pe2, *plog, *pagg;
    int *pdeg, *pcur, *poff, *pel, *pdst, *psrc;
    cudaGetSymbolAddress((void**)&pS1, g_S1);
    cudaGetSymbolAddress((void**)&pT1, g_T1);
    cudaGetSymbolAddress((void**)&pSv, g_Sv);
    cudaGetSymbolAddress((void**)&pe1, g_e1);
    cudaGetSymbolAddress((void**)&pe2, g_e2);
    cudaGetSymbolAddress((void**)&plog, g_logits);
    cudaGetSymbolAddress((void**)&pagg, g_agg);
    cudaGetSymbolAddress((void**)&pdeg, g_deg);
    cudaGetSymbolAddress((void**)&pcur, g_cur);
    cudaGetSymbolAddress((void**)&poff, g_off);
    cudaGetSymbolAddress((void**)&pel, g_elist);
    cudaGetSymbolAddress((void**)&pdst, g_dst);
    cudaGetSymbolAddress((void**)&psrc, g_src);

    cudaFuncSetAttribute(mma_gemm, cudaFuncAttributeMaxDynamicSharedMemorySize,
                         SMEM_BYTES);

    dim3 gn((NN + 127) / 128, 2);   // 79 x 2
    dim3 ge(EE / 128, 2);           // 2500 x 2

    // 1-2: index normalize (R7 order throughout)
    k_sniff<<<1, 128>>>((const int*)eidx);
    k_convert<<<(EE + 255) / 256, 256>>>(eidx, pdst, psrc);

    // 3-5: node precomputes
    mma_gemm<<<gn, 256, SMEM_BYTES>>>(src_na, 256, Wb1, 768, nullptr,
        nullptr, nullptr, nullptr, nullptr, pS1, NN, 0, nullptr, nullptr);
    mma_gemm<<<gn, 256, SMEM_BYTES>>>(dst_na, 256, Wb1 + 512, 768, nullptr,
        nullptr, nullptr, nullptr, nullptr, pT1, NN, 0, nullptr, nullptr);
    mma_gemm<<<gn, 256, SMEM_BYTES>>>(src_na, 256, Wv1, 512, nullptr,
        nullptr, nullptr, nullptr, nullptr, pSv, NN, 0, nullptr, nullptr);

    // 6: edge h1 = relu(ea@Wb1_e^T + S1[src] + T1[dst] + bb1)
    mma_gemm<<<ge, 256, SMEM_BYTES>>>(ea, 256, Wb1 + 256, 768, bb1,
        pS1, psrc, pT1, pdst, pe1, EE, 1, nullptr, nullptr);

    // 7-8: logits init, fused h2+logits (h2 never materialized)
    k_initlog<<<(EE * NHD) / 256, 256>>>(bb3, plog);
    mma_gemm<<<ge, 256, SMEM_BYTES>>>(pe1, 256, Wb2, 256, bb2,
        nullptr, nullptr, nullptr, nullptr, nullptr, EE, 3, Wb3, plog);

    // 9: v1 = gelu(ea@Wv1_e^T + Sv[src] + bv1)
    mma_gemm<<<ge, 256, SMEM_BYTES>>>(ea, 256, Wv1 + 256, 512, bv1,
        pSv, psrc, nullptr, nullptr, pe2, EE, 2, nullptr, nullptr);

    // 10-13: CSR build
    k_zero<<<(NN + 255) / 256, 256>>>(pdeg, pcur, NN);
    k_count<<<EE / 256, 256>>>(pdst, pdeg);
    k_scan<<<1, 1024>>>(pdeg, poff);
    k_fill<<<EE / 256, 256>>>(pdst, poff, pcur, pel);

    // 14-15: v2, V
    mma_gemm<<<ge, 256, SMEM_BYTES>>>(pe2, 256, Wv2, 256, bv2,
        nullptr, nullptr, nullptr, nullptr, pe1, EE, 2, nullptr, nullptr);
    mma_gemm<<<ge, 256, SMEM_BYTES>>>(pe1, 256, Wv3, 256, bv3,
        nullptr, nullptr, nullptr, nullptr, pe2, EE, 0, nullptr, nullptr);

    // 16: per-node softmax + aggregation
    k_softmax_agg<<<NN, 256>>>(plog, pe2, poff, pel, pagg);

    // 17: output projection
    mma_gemm<<<gn, 256, SMEM_BYTES>>>(pagg, 256, WO, 256, nullptr,
        nullptr, nullptr, nullptr, nullptr, (float*)d_out, NN, 0,
        nullptr, nullptr);
}

// round 13
// speedup vs baseline: 1.5354x; 1.1462x over previous
#include <cuda_runtime.h>
#include <cuda_bf16.h>
#include <cuda_fp16.h>
#include <stdint.h>
#include <math.h>

#define NN 10000
#define EE 320000
#define HH 256
#define NHD 8

// ---------------- scratch (static device globals; no runtime alloc) --------
__device__ float g_S1[NN * HH];
__device__ float g_T1[NN * HH];
__device__ float g_Sv[NN * HH];
__device__ float g_e1[(size_t)EE * HH];
__device__ float g_e2[(size_t)EE * HH];
__device__ float g_logits[(size_t)EE * NHD];
__device__ float g_agg[NN * HH];
__device__ int   g_deg[NN];
__device__ int   g_cur[NN];
__device__ int   g_off[NN + 1];
__device__ int   g_elist[EE];
__device__ int   g_dst[EE];
__device__ int   g_src[EE];
__device__ int   g_is64;

__device__ __forceinline__ float gelu_f(float x) {
    return 0.5f * x * (1.0f + erff(x * 0.7071067811865476f));
}

__device__ __forceinline__ unsigned int pack_h2(float lo, float hi) {
    __half2 h = __floats2half2_rn(lo, hi);
    return *reinterpret_cast<unsigned int*>(&h);
}

// m16n8k16 fp16 mma (row.col), fp32 accumulate
__device__ __forceinline__ void mma_f16(float* c, const unsigned int* a,
                                        const unsigned int* b) {
    asm volatile(
        "mma.sync.aligned.m16n8k16.row.col.f32.f16.f16.f32 "
        "{%0,%1,%2,%3}, {%4,%5,%6,%7}, {%8,%9}, {%0,%1,%2,%3};"
        : "+f"(c[0]), "+f"(c[1]), "+f"(c[2]), "+f"(c[3])
        : "r"(a[0]), "r"(a[1]), "r"(a[2]), "r"(a[3]), "r"(b[0]), "r"(b[1]));
}

__device__ __forceinline__ unsigned int smem_u32(const void* p) {
    unsigned int a;
    asm("{ .reg .u64 t; cvta.to.shared.u64 t, %1; cvt.u32.u64 %0, t; }"
        : "=r"(a) : "l"(p));
    return a;
}

__device__ __forceinline__ void ldsm_x4(unsigned int* r, unsigned int addr) {
    asm volatile(
        "ldmatrix.sync.aligned.m8n8.x4.shared.b16 {%0,%1,%2,%3}, [%4];"
        : "=r"(r[0]), "=r"(r[1]), "=r"(r[2]), "=r"(r[3]) : "r"(addr));
}
__device__ __forceinline__ void ldsm_x2(unsigned int* r, unsigned int addr) {
    asm volatile(
        "ldmatrix.sync.aligned.m8n8.x2.shared.b16 {%0,%1}, [%2];"
        : "=r"(r[0]), "=r"(r[1]) : "r"(addr));
}

// ---------------- fp16 mma.sync GEMM: C = act(A @ W^T + bias + gathers) ----
// CTA tile 128 x 128 (grid.y over 2 N-halves). K=256, 8 dbl-buffered chunks.
// fp16 operands (same 10-bit mantissa as tf32), fp32 accumulate.
// act: 0 none, 1 relu, 2 gelu, 3 relu + fused logits projection (no C write)
#define HSTR 40                        // halves per smem row (32 + 8 pad)
#define BUF_H (128 * HSTR)             // 5120 halves = 10240 B per buffer
#define BUF_B (BUF_H * 2)
#define SMEM_BYTES 73728               // 4 bufs (40960) + epilogue stage reuse

__global__ void __launch_bounds__(256, 2) mma_gemm(
    const float* __restrict__ A, int lda,
    const float* __restrict__ W, int ldw,
    const float* __restrict__ bias,
    const float* __restrict__ add1, const int* __restrict__ idx1,
    const float* __restrict__ add2, const int* __restrict__ idx2,
    float* __restrict__ C, int M, int act,
    const float* __restrict__ Wb3, float* __restrict__ logits)
{
    extern __shared__ float smf[];
    unsigned int* smw = reinterpret_cast<unsigned int*>(smf);
    const unsigned int smb = smem_u32(smf);

    const int tid = threadIdx.x;
    const int wid = tid >> 5;
    const int lane = tid & 31;
    const int warp_m = wid & 1;
    const int warp_n = wid >> 1;
    const int qr = lane >> 2;
    const int qc = lane & 3;
    const int m0 = blockIdx.x * 128;
    const int n0 = blockIdx.y * 128;

    // ldmatrix per-lane byte-offset constants
    const int lm = lane >> 3;             // A matrix index 0..3
    const int lr8 = lane & 7;
    // A matrices: m0=(rows+0,k0-7) m1=(rows+8,k0-7) m2=(rows+0,k8-15) m3=(rows+8,k8-15)
    const int a_lane_b = (warp_m * 64 + ((lm & 1) << 3) + lr8) * 80
                       + (((lm >> 1) << 3) << 1);
    const int blm = (lane & 15) >> 3;     // B matrix index 0..1
    const int b_lane_b = (warp_n * 32 + lr8) * 80 + (blm << 4);

    float c[4][4][4];
#pragma unroll
    for (int i = 0; i < 4; i++)
#pragma unroll
        for (int j = 0; j < 4; j++)
#pragma unroll
            for (int q = 0; q < 4; q++) c[i][j][q] = 0.f;

    float4 ra[4], rb[4];

    auto load_regs = [&](int kc) {
        const int kcol = kc * 32;
#pragma unroll
        for (int it = 0; it < 4; it++) {
            int idx = tid + it * 256;
            int r = idx >> 3, f4 = idx & 7;
            ra[it] = make_float4(0.f, 0.f, 0.f, 0.f);
            if (m0 + r < M)
                ra[it] = *reinterpret_cast<const float4*>(
                    A + (size_t)(m0 + r) * lda + kcol + f4 * 4);
            rb[it] = *reinterpret_cast<const float4*>(
                W + (size_t)(n0 + r) * ldw + kcol + f4 * 4);
        }
    };
    auto store_regs = [&](int buf) {
        unsigned int* sA = smw + buf * (BUF_B / 4);
        unsigned int* sB = smw + (2 + buf) * (BUF_B / 4);
#pragma unroll
        for (int it = 0; it < 4; it++) {
            int idx = tid + it * 256;
            int r = idx >> 3, f4 = idx & 7;
            uint2 ta, tb;
            ta.x = pack_h2(ra[it].x, ra[it].y);
            ta.y = pack_h2(ra[it].z, ra[it].w);
            tb.x = pack_h2(rb[it].x, rb[it].y);
            tb.y = pack_h2(rb[it].z, rb[it].w);
            *reinterpret_cast<uint2*>(sA + r * 20 + f4 * 2) = ta;
            *reinterpret_cast<uint2*>(sB + r * 20 + f4 * 2) = tb;
        }
    };
    auto mma_k = [&](int b, int ks) {
        const unsigned int baseA = smb + b * BUF_B;
        const unsigned int baseB = smb + (2 + b) * BUF_B;
        unsigned int af[4][4], bf[4][2];
#pragma unroll
        for (int mt = 0; mt < 4; mt++)
            ldsm_x4(af[mt],
                    baseA + (unsigned)(a_lane_b + mt * 1280 + ks * 32));
#pragma unroll
        for (int nt = 0; nt < 4; nt++)
            ldsm_x2(bf[nt],
                    baseB + (unsigned)(b_lane_b + nt * 640 + ks * 32));
#pragma unroll
        for (int mt = 0; mt < 4; mt++)
#pragma unroll
            for (int nt = 0; nt < 4; nt++)
                mma_f16(c[mt][nt], af[mt], bf[nt]);
    };

    load_regs(0);
    store_regs(0);
    __syncthreads();

#pragma unroll 1
    for (int kc = 0; kc < 8; kc++) {
        const int b = kc & 1;
        if (kc < 7) load_regs(kc + 1);     // LDGs in flight during MMAs
        mma_k(b, 0);
        if (kc < 7) store_regs(b ^ 1);     // cvt+STS after latency covered
        mma_k(b, 1);
        __syncthreads();
    }

    // ---- stage accumulators in smem (128 x 132) ----
    float* stage = smf;
#pragma unroll
    for (int mt = 0; mt < 4; mt++) {
#pragma unroll
        for (int nt = 0; nt < 4; nt++) {
            int row = warp_m * 64 + mt * 16 + qr;
            int col = warp_n * 32 + nt * 8 + qc * 2;
            *reinterpret_cast<float2*>(stage + row * 132 + col) =
                make_float2(c[mt][nt][0], c[mt][nt][1]);
            *reinterpret_cast<float2*>(stage + (row + 8) * 132 + col) =
                make_float2(c[mt][nt][2], c[mt][nt][3]);
        }
    }
    __syncthreads();

    if (act == 3) {
        // fused logits: logits[m][h] += sum_n relu(h2_mn) * Wb3[h][n]/sqrt(d)
        float* sW3 = smf + 128 * 132;          // 8 x 128
        float* sb = sW3 + 1024;                // 128
        for (int i = tid; i < 1024; i += 256)
            sW3[i] = Wb3[(i >> 7) * 256 + n0 + (i & 127)];
        if (tid < 128) sb[tid] = bias[n0 + tid];
        __syncthreads();

        int row = tid >> 1, half = tid & 1;
        int m = m0 + row;
        float acc[NHD];
#pragma unroll
        for (int h = 0; h < NHD; h++) acc[h] = 0.f;
        const float* srow = smf + row * 132 + half * 64;
        const float* brow = sb + half * 64;
        const float* wrow = sW3 + half * 64;
#pragma unroll 8
        for (int cc = 0; cc < 64; cc++) {
            float v = fmaxf(srow[cc] + brow[cc], 0.f);
#pragma unroll
            for (int h = 0; h < NHD; h++) acc[h] += v * wrow[h * 128 + cc];
        }
#pragma unroll
        for (int h = 0; h < NHD; h++)
            atomicAdd(&logits[(size_t)m * NHD + h],
                      acc[h] * 0.17677669529663687f);
        return;
    }

    // ---- fused epilogue, float4 coalesced ----
#pragma unroll 4
    for (int i = 0; i < 16; i++) {
        int idx = i * 256 + tid;
        int row = idx >> 5;
        int col = (idx & 31) * 4;
        int m = m0 + row, n = n0 + col;
        if (m < M) {
            float4 v = *reinterpret_cast<float4*>(stage + row * 132 + col);
            if (bias) {
                float4 bv = *reinterpret_cast<const float4*>(bias + n);
                v.x += bv.x; v.y += bv.y; v.z += bv.z; v.w += bv.w;
            }
            if (add1) {
                float4 a = *reinterpret_cast<const float4*>(
                    add1 + (size_t)idx1[m] * 256 + n);
                v.x += a.x; v.y += a.y; v.z += a.z; v.w += a.w;
            }
            if (add2) {
                float4 a = *reinterpret_cast<const float4*>(
                    add2 + (size_t)idx2[m] * 256 + n);
                v.x += a.x; v.y += a.y; v.z += a.z; v.w += a.w;
            }
            if (act == 1) {
                v.x = fmaxf(v.x, 0.f); v.y = fmaxf(v.y, 0.f);
                v.z = fmaxf(v.z, 0.f); v.w = fmaxf(v.w, 0.f);
            } else if (act == 2) {
                v.x = gelu_f(v.x); v.y = gelu_f(v.y);
                v.z = gelu_f(v.z); v.w = gelu_f(v.w);
            }
            *reinterpret_cast<float4*>(C + (size_t)m * 256 + n) = v;
        }
    }
}

// ---------------- logits init: bb3 broadcast * 1/sqrt(d) -------------------
__global__ void k_initlog(const float* __restrict__ bb3,
                          float* __restrict__ logits) {
    int i = blockIdx.x * 256 + threadIdx.x;
    if (i < EE * NHD)
        logits[i] = __ldg(bb3 + (i & 7)) * 0.17677669529663687f;
}

// ---------------- index dtype sniff + normalize ----------------------------
__global__ void k_sniff(const int* __restrict__ buf) {
    __shared__ int nz;
    if (threadIdx.x == 0) nz = 0;
    __syncthreads();
    int w = buf[threadIdx.x * 2 + 1];
    if (w != 0) atomicOr(&nz, 1);
    __syncthreads();
    if (threadIdx.x == 0) g_is64 = nz ? 0 : 1;
}

__global__ void k_convert(const void* __restrict__ buf,
                          int* __restrict__ dst, int* __restrict__ src) {
    int e = blockIdx.x * 256 + threadIdx.x;
    if (e >= EE) return;
    if (g_is64) {
        const long long* p = (const long long*)buf;
        dst[e] = (int)p[e];
        src[e] = (int)p[EE + e];
    } else {
        const int* p = (const int*)buf;
        dst[e] = p[e];
        src[e] = p[EE + e];
    }
}

// ---------------- CSR build -------------------------------------------------
__global__ void k_zero(int* a, int* b, int n) {
    int i = blockIdx.x * blockDim.x + threadIdx.x;
    if (i < n) { a[i] = 0; b[i] = 0; }
}

__global__ void k_count(const int* __restrict__ dst, int* __restrict__ deg) {
    int e = blockIdx.x * 256 + threadIdx.x;
    if (e < EE) atomicAdd(&deg[dst[e]], 1);
}

__global__ void __launch_bounds__(1024) k_scan(
    const int* __restrict__ deg, int* __restrict__ off)
{
    __shared__ int ssum[1024];
    const int t = threadIdx.x;
    const int ITEMS = 10;
    int base = t * ITEMS;
    int loc[ITEMS];
    int s = 0;
#pragma unroll
    for (int i = 0; i < ITEMS; i++) {
        int v = (base + i < NN) ? deg[base + i] : 0;
        loc[i] = s;
        s += v;
    }
    ssum[t] = s;
    __syncthreads();
    for (int d = 1; d < 1024; d <<= 1) {
        int v = (t >= d) ? ssum[t - d] : 0;
        __syncthreads();
        if (t >= d) ssum[t] += v;
        __syncthreads();
    }
    int excl = (t == 0) ? 0 : ssum[t - 1];
#pragma unroll
    for (int i = 0; i < ITEMS; i++)
        if (base + i < NN) off[base + i] = excl + loc[i];
    if (t == 0) off[NN] = ssum[1023];
}

__global__ void k_fill(const int* __restrict__ dst,
                       const int* __restrict__ off, int* __restrict__ cur,
                       int* __restrict__ elist)
{
    int e = blockIdx.x * 256 + threadIdx.x;
    if (e < EE) {
        int d = dst[e];
        int p = off[d] + atomicAdd(&cur[d], 1);
        elist[p] = e;
    }
}

// ---------------- per-node softmax + weighted aggregation ------------------
__global__ void __launch_bounds__(256) k_softmax_agg(
    const float* __restrict__ logits, const float* __restrict__ V,
    const int* __restrict__ off, const int* __restrict__ elist,
    float* __restrict__ agg)
{
    int n = blockIdx.x;
    int tid = threadIdx.x;
    int lane = tid & 31;
    int w = tid >> 5;

    int s = off[n];
    int deg = off[n + 1] - s;
    if (deg == 0) { agg[(size_t)n * HH + tid] = 0.f; return; }

    __shared__ float s_m[NHD], s_d[NHD];
    __shared__ int s_eid[64];

    float mx = -INFINITY;
    for (int i = lane; i < deg; i += 32)
        mx = fmaxf(mx, logits[(size_t)elist[s + i] * NHD + w]);
#pragma unroll
    for (int o = 16; o; o >>= 1) mx = fmaxf(mx, __shfl_xor_sync(0xffffffffu, mx, o));
    float sum = 0.f;
    for (int i = lane; i < deg; i += 32)
        sum += expf(logits[(size_t)elist[s + i] * NHD + w] - mx);
#pragma unroll
    for (int o = 16; o; o >>= 1) sum += __shfl_xor_sync(0xffffffffu, sum, o);
    if (lane == 0) { s_m[w] = mx; s_d[w] = sum; }
    __syncthreads();

    float m_h = s_m[w];
    float inv_d = 1.0f / s_d[w];

    float acc = 0.f;
    for (int c0 = 0; c0 < deg; c0 += 64) {
        int len = min(64, deg - c0);
        __syncthreads();
        if (tid < len) s_eid[tid] = elist[s + c0 + tid];
        __syncthreads();
        float a0 = 0.f, a1 = 0.f;
        if (lane < len)
            a0 = expf(logits[(size_t)s_eid[lane] * NHD + w] - m_h) * inv_d;
        if (32 + lane < len)
            a1 = expf(logits[(size_t)s_eid[32 + lane] * NHD + w] - m_h) * inv_d;
        for (int i = 0; i < len; i++) {
            float av = (i < 32) ? a0 : a1;
            float att = __shfl_sync(0xffffffffu, av, i & 31);
            acc += att * __ldg(V + (size_t)s_eid[i] * HH + tid);
        }
    }
    agg[(size_t)n * HH + tid] = acc;
}

// ---------------- launch ----------------------------------------------------
extern "C" void kernel_launch(void* const* d_in, const int* in_sizes, int n_in,
                              void* d_out, int out_size)
{
    const float* src_na = (const float*)d_in[0];
    const float* dst_na = (const float*)d_in[1];
    const float* ea     = (const float*)d_in[2];
    const void*  eidx   = d_in[3];
    const float* Wv1 = (const float*)d_in[4];
    const float* bv1 = (const float*)d_in[5];
    const float* Wv2 = (const float*)d_in[6];
    const float* bv2 = (const float*)d_in[7];
    const float* Wv3 = (const float*)d_in[8];
    const float* bv3 = (const float*)d_in[9];
    const float* Wb1 = (const float*)d_in[10];
    const float* bb1 = (const float*)d_in[11];
    const float* Wb2 = (const float*)d_in[12];
    const float* bb2 = (const float*)d_in[13];
    const float* Wb3 = (const float*)d_in[14];
    const float* bb3 = (const float*)d_in[15];
    const float* WO  = (const float*)d_in[16];

    float *pS1, *pT1, *pSv, *pe1, *pe2, *plog, *pagg;
    int *pdeg, *pcur, *poff, *pel, *pdst, *psrc;
    cudaGetSymbolAddress((void**)&pS1, g_S1);
    cudaGetSymbolAddress((void**)&pT1, g_T1);
    cudaGetSymbolAddress((void**)&pSv, g_Sv);
    cudaGetSymbolAddress((void**)&pe1, g_e1);
    cudaGetSymbolAddress((void**)&pe2, g_e2);
    cudaGetSymbolAddress((void**)&plog, g_logits);
    cudaGetSymbolAddress((void**)&pagg, g_agg);
    cudaGetSymbolAddress((void**)&pdeg, g_deg);
    cudaGetSymbolAddress((void**)&pcur, g_cur);
    cudaGetSymbolAddress((void**)&poff, g_off);
    cudaGetSymbolAddress((void**)&pel, g_elist);
    cudaGetSymbolAddress((void**)&pdst, g_dst);
    cudaGetSymbolAddress((void**)&psrc, g_src);

    cudaFuncSetAttribute(mma_gemm, cudaFuncAttributeMaxDynamicSharedMemorySize,
                         SMEM_BYTES);

    dim3 gn((NN + 127) / 128, 2);   // 79 x 2
    dim3 ge(EE / 128, 2);           // 2500 x 2

    // 1-2: index normalize
    k_sniff<<<1, 128>>>((const int*)eidx);
    k_convert<<<(EE + 255) / 256, 256>>>(eidx, pdst, psrc);

    // 3-5: node precomputes
    mma_gemm<<<gn, 256, SMEM_BYTES>>>(src_na, 256, Wb1, 768, nullptr,
        nullptr, nullptr, nullptr, nullptr, pS1, NN, 0, nullptr, nullptr);
    mma_gemm<<<gn, 256, SMEM_BYTES>>>(dst_na, 256, Wb1 + 512, 768, nullptr,
        nullptr, nullptr, nullptr, nullptr, pT1, NN, 0, nullptr, nullptr);
    mma_gemm<<<gn, 256, SMEM_BYTES>>>(src_na, 256, Wv1, 512, nullptr,
        nullptr, nullptr, nullptr, nullptr, pSv, NN, 0, nullptr, nullptr);

    // 6: edge h1 = relu(ea@Wb1_e^T + S1[src] + T1[dst] + bb1)
    mma_gemm<<<ge, 256, SMEM_BYTES>>>(ea, 256, Wb1 + 256, 768, bb1,
        pS1, psrc, pT1, pdst, pe1, EE, 1, nullptr, nullptr);

    // 7-8: logits init, fused h2+logits (h2 never materialized)
    k_initlog<<<(EE * NHD) / 256, 256>>>(bb3, plog);
    mma_gemm<<<ge, 256, SMEM_BYTES>>>(pe1, 256, Wb2, 256, bb2,
        nullptr, nullptr, nullptr, nullptr, nullptr, EE, 3, Wb3, plog);

    // 9: v1 = gelu(ea@Wv1_e^T + Sv[src] + bv1)
    mma_gemm<<<ge, 256, SMEM_BYTES>>>(ea, 256, Wv1 + 256, 512, bv1,
        pSv, psrc, nullptr, nullptr, pe2, EE, 2, nullptr, nullptr);

    // 10-13: CSR build
    k_zero<<<(NN + 255) / 256, 256>>>(pdeg, pcur, NN);
    k_count<<<EE / 256, 256>>>(pdst, pdeg);
    k_scan<<<1, 1024>>>(pdeg, poff);
    k_fill<<<EE / 256, 256>>>(pdst, poff, pcur, pel);

    // 14-15: v2, V
    mma_gemm<<<ge, 256, SMEM_BYTES>>>(pe2, 256, Wv2, 256, bv2,
        nullptr, nullptr, nullptr, nullptr, pe1, EE, 2, nullptr, nullptr);
    mma_gemm<<<ge, 256, SMEM_BYTES>>>(pe1, 256, Wv3, 256, bv3,
        nullptr, nullptr, nullptr, nullptr, pe2, EE, 0, nullptr, nullptr);

    // 16: per-node softmax + aggregation
    k_softmax_agg<<<NN, 256>>>(plog, pe2, poff, pel, pagg);

    // 17: output projection
    mma_gemm<<<gn, 256, SMEM_BYTES>>>(pagg, 256, WO, 256, nullptr,
        nullptr, nullptr, nullptr, nullptr, (float*)d_out, NN, 0,
        nullptr, nullptr);
}

// round 14
// speedup vs baseline: 1.6488x; 1.0738x over previous
#include <cuda_runtime.h>
#include <cuda_bf16.h>
#include <cuda_fp16.h>
#include <stdint.h>
#include <math.h>

#define NN 10000
#define EE 320000
#define HH 256
#define NHD 8

// ---------------- scratch (static device globals; no runtime alloc) --------
__device__ float g_S1[NN * HH];
__device__ float g_T1[NN * HH];
__device__ float g_Sv[NN * HH];
__device__ float g_e1[(size_t)EE * HH];   // used as half or float per stage
__device__ float g_e2[(size_t)EE * HH];
__device__ float g_logits[(size_t)EE * NHD];
__device__ float g_agg[NN * HH];
__device__ int   g_deg[NN];
__device__ int   g_cur[NN];
__device__ int   g_off[NN + 1];
__device__ int   g_elist[EE];
__device__ int   g_dst[EE];
__device__ int   g_src[EE];
__device__ int   g_is64;

__device__ __forceinline__ float gelu_f(float x) {
    return 0.5f * x * (1.0f + erff(x * 0.7071067811865476f));
}

__device__ __forceinline__ unsigned int pack_h2(float lo, float hi) {
    __half2 h = __floats2half2_rn(lo, hi);
    return *reinterpret_cast<unsigned int*>(&h);
}

// m16n8k16 fp16 mma (row.col), fp32 accumulate
__device__ __forceinline__ void mma_f16(float* c, const unsigned int* a,
                                        const unsigned int* b) {
    asm volatile(
        "mma.sync.aligned.m16n8k16.row.col.f32.f16.f16.f32 "
        "{%0,%1,%2,%3}, {%4,%5,%6,%7}, {%8,%9}, {%0,%1,%2,%3};"
        : "+f"(c[0]), "+f"(c[1]), "+f"(c[2]), "+f"(c[3])
        : "r"(a[0]), "r"(a[1]), "r"(a[2]), "r"(a[3]), "r"(b[0]), "r"(b[1]));
}

__device__ __forceinline__ unsigned int smem_u32(const void* p) {
    unsigned int a;
    asm("{ .reg .u64 t; cvta.to.shared.u64 t, %1; cvt.u32.u64 %0, t; }"
        : "=r"(a) : "l"(p));
    return a;
}

__device__ __forceinline__ void ldsm_x4(unsigned int* r, unsigned int addr) {
    asm volatile(
        "ldmatrix.sync.aligned.m8n8.x4.shared.b16 {%0,%1,%2,%3}, [%4];"
        : "=r"(r[0]), "=r"(r[1]), "=r"(r[2]), "=r"(r[3]) : "r"(addr));
}
__device__ __forceinline__ void ldsm_x2(unsigned int* r, unsigned int addr) {
    asm volatile(
        "ldmatrix.sync.aligned.m8n8.x2.shared.b16 {%0,%1}, [%2];"
        : "=r"(r[0]), "=r"(r[1]) : "r"(addr));
}

// ---------------- fp16 mma.sync GEMM: C = act(A @ W^T + bias + gathers) ----
// AHALF: A is fp16 (direct STS, no cvt). CHALF: C written as fp16.
// CTA tile 128 x 128 (grid.y over 2 N-halves). K=256, 8 dbl-buffered chunks.
// act: 0 none, 1 relu, 2 gelu, 3 relu + fused logits projection (no C write)
#define HSTR 40                        // halves per smem row (32 + 8 pad)
#define BUF_H (128 * HSTR)             // 5120 halves = 10240 B per buffer
#define BUF_B (BUF_H * 2)
#define SMEM_BYTES 73728               // 4 bufs (40960) + epilogue stage reuse

template <bool AHALF, bool CHALF>
__global__ void __launch_bounds__(256, 2) mma_gemm(
    const void* __restrict__ Av, int lda,
    const float* __restrict__ W, int ldw,
    const float* __restrict__ bias,
    const float* __restrict__ add1, const int* __restrict__ idx1,
    const float* __restrict__ add2, const int* __restrict__ idx2,
    void* __restrict__ Cv, int M, int act,
    const float* __restrict__ Wb3, float* __restrict__ logits)
{
    extern __shared__ float smf[];
    unsigned int* smw = reinterpret_cast<unsigned int*>(smf);
    char* smc = reinterpret_cast<char*>(smf);
    const unsigned int smb = smem_u32(smf);

    const int tid = threadIdx.x;
    const int wid = tid >> 5;
    const int lane = tid & 31;
    const int warp_m = wid & 1;
    const int warp_n = wid >> 1;
    const int qr = lane >> 2;
    const int qc = lane & 3;
    const int m0 = blockIdx.x * 128;
    const int n0 = blockIdx.y * 128;

    // ldmatrix per-lane byte-offset constants (layout proven in R13)
    const int lm = lane >> 3;
    const int lr8 = lane & 7;
    const int a_lane_b = (warp_m * 64 + ((lm & 1) << 3) + lr8) * 80
                       + (((lm >> 1) << 3) << 1);
    const int blm = (lane & 15) >> 3;
    const int b_lane_b = (warp_n * 32 + lr8) * 80 + (blm << 4);

    float c[4][4][4];
#pragma unroll
    for (int i = 0; i < 4; i++)
#pragma unroll
        for (int j = 0; j < 4; j++)
#pragma unroll
            for (int q = 0; q < 4; q++) c[i][j][q] = 0.f;

    float4 ra[4], rb[4];
    uint4 ha[2];

    auto load_regs = [&](int kc) {
        const int kcol = kc * 32;
        if (AHALF) {
            const __half* Ah = (const __half*)Av;
#pragma unroll
            for (int it = 0; it < 2; it++) {
                int idx = tid + it * 256;
                int r = idx >> 2, q = idx & 3;
                ha[it] = make_uint4(0u, 0u, 0u, 0u);
                if (m0 + r < M)
                    ha[it] = *reinterpret_cast<const uint4*>(
                        Ah + (size_t)(m0 + r) * lda + kcol + q * 8);
            }
        } else {
            const float* Af = (const float*)Av;
#pragma unroll
            for (int it = 0; it < 4; it++) {
                int idx = tid + it * 256;
                int r = idx >> 3, f4 = idx & 7;
                ra[it] = make_float4(0.f, 0.f, 0.f, 0.f);
                if (m0 + r < M)
                    ra[it] = *reinterpret_cast<const float4*>(
                        Af + (size_t)(m0 + r) * lda + kcol + f4 * 4);
            }
        }
#pragma unroll
        for (int it = 0; it < 4; it++) {
            int idx = tid + it * 256;
            int r = idx >> 3, f4 = idx & 7;
            rb[it] = *reinterpret_cast<const float4*>(
                W + (size_t)(n0 + r) * ldw + kcol + f4 * 4);
        }
    };
    auto store_regs = [&](int buf) {
        if (AHALF) {
            char* sA = smc + buf * BUF_B;
#pragma unroll
            for (int it = 0; it < 2; it++) {
                int idx = tid + it * 256;
                int r = idx >> 2, q = idx & 3;
                *reinterpret_cast<uint4*>(sA + r * 80 + q * 16) = ha[it];
            }
        } else {
            unsigned int* sA = smw + buf * (BUF_B / 4);
#pragma unroll
            for (int it = 0; it < 4; it++) {
                int idx = tid + it * 256;
                int r = idx >> 3, f4 = idx & 7;
                uint2 ta;
                ta.x = pack_h2(ra[it].x, ra[it].y);
                ta.y = pack_h2(ra[it].z, ra[it].w);
                *reinterpret_cast<uint2*>(sA + r * 20 + f4 * 2) = ta;
            }
        }
        unsigned int* sB = smw + (2 + buf) * (BUF_B / 4);
#pragma unroll
        for (int it = 0; it < 4; it++) {
            int idx = tid + it * 256;
            int r = idx >> 3, f4 = idx & 7;
            uint2 tb;
            tb.x = pack_h2(rb[it].x, rb[it].y);
            tb.y = pack_h2(rb[it].z, rb[it].w);
            *reinterpret_cast<uint2*>(sB + r * 20 + f4 * 2) = tb;
        }
    };
    auto mma_k = [&](int b, int ks) {
        const unsigned int baseA = smb + b * BUF_B;
        const unsigned int baseB = smb + (2 + b) * BUF_B;
        unsigned int af[4][4], bf[4][2];
#pragma unroll
        for (int mt = 0; mt < 4; mt++)
            ldsm_x4(af[mt],
                    baseA + (unsigned)(a_lane_b + mt * 1280 + ks * 32));
#pragma unroll
        for (int nt = 0; nt < 4; nt++)
            ldsm_x2(bf[nt],
                    baseB + (unsigned)(b_lane_b + nt * 640 + ks * 32));
#pragma unroll
        for (int mt = 0; mt < 4; mt++)
#pragma unroll
            for (int nt = 0; nt < 4; nt++)
                mma_f16(c[mt][nt], af[mt], bf[nt]);
    };

    load_regs(0);
    store_regs(0);
    __syncthreads();

#pragma unroll 1
    for (int kc = 0; kc < 8; kc++) {
        const int b = kc & 1;
        if (kc < 7) load_regs(kc + 1);     // LDGs in flight during MMAs
        mma_k(b, 0);
        if (kc < 7) store_regs(b ^ 1);     // cvt+STS after latency covered
        mma_k(b, 1);
        __syncthreads();
    }

    // ---- stage accumulators in smem (128 x 132) ----
    float* stage = smf;
#pragma unroll
    for (int mt = 0; mt < 4; mt++) {
#pragma unroll
        for (int nt = 0; nt < 4; nt++) {
            int row = warp_m * 64 + mt * 16 + qr;
            int col = warp_n * 32 + nt * 8 + qc * 2;
            *reinterpret_cast<float2*>(stage + row * 132 + col) =
                make_float2(c[mt][nt][0], c[mt][nt][1]);
            *reinterpret_cast<float2*>(stage + (row + 8) * 132 + col) =
                make_float2(c[mt][nt][2], c[mt][nt][3]);
        }
    }
    __syncthreads();

    if (act == 3) {
        // fused logits: logits[m][h] += sum_n relu(h2_mn) * Wb3[h][n]/sqrt(d)
        float* sW3 = smf + 128 * 132;          // 8 x 128
        float* sb = sW3 + 1024;                // 128
        for (int i = tid; i < 1024; i += 256)
            sW3[i] = Wb3[(i >> 7) * 256 + n0 + (i & 127)];
        if (tid < 128) sb[tid] = bias[n0 + tid];
        __syncthreads();

        int row = tid >> 1, half = tid & 1;
        int m = m0 + row;
        float acc[NHD];
#pragma unroll
        for (int h = 0; h < NHD; h++) acc[h] = 0.f;
        const float* srow = smf + row * 132 + half * 64;
        const float* brow = sb + half * 64;
        const float* wrow = sW3 + half * 64;
#pragma unroll 8
        for (int cc = 0; cc < 64; cc++) {
            float v = fmaxf(srow[cc] + brow[cc], 0.f);
#pragma unroll
            for (int h = 0; h < NHD; h++) acc[h] += v * wrow[h * 128 + cc];
        }
#pragma unroll
        for (int h = 0; h < NHD; h++)
            atomicAdd(&logits[(size_t)m * NHD + h],
                      acc[h] * 0.17677669529663687f);
        return;
    }

    // ---- fused epilogue, coalesced (float4 or half2x2) ----
#pragma unroll 4
    for (int i = 0; i < 16; i++) {
        int idx = i * 256 + tid;
        int row = idx >> 5;
        int col = (idx & 31) * 4;
        int m = m0 + row, n = n0 + col;
        if (m < M) {
            float4 v = *reinterpret_cast<float4*>(stage + row * 132 + col);
            if (bias) {
                float4 bv = *reinterpret_cast<const float4*>(bias + n);
                v.x += bv.x; v.y += bv.y; v.z += bv.z; v.w += bv.w;
            }
            if (add1) {
                float4 a = *reinterpret_cast<const float4*>(
                    add1 + (size_t)idx1[m] * 256 + n);
                v.x += a.x; v.y += a.y; v.z += a.z; v.w += a.w;
            }
            if (add2) {
                float4 a = *reinterpret_cast<const float4*>(
                    add2 + (size_t)idx2[m] * 256 + n);
                v.x += a.x; v.y += a.y; v.z += a.z; v.w += a.w;
            }
            if (act == 1) {
                v.x = fmaxf(v.x, 0.f); v.y = fmaxf(v.y, 0.f);
                v.z = fmaxf(v.z, 0.f); v.w = fmaxf(v.w, 0.f);
            } else if (act == 2) {
                v.x = gelu_f(v.x); v.y = gelu_f(v.y);
                v.z = gelu_f(v.z); v.w = gelu_f(v.w);
            }
            if (CHALF) {
                __half* Ch = (__half*)Cv;
                uint2 o;
                o.x = pack_h2(v.x, v.y);
                o.y = pack_h2(v.z, v.w);
                *reinterpret_cast<uint2*>(Ch + (size_t)m * 256 + n) = o;
            } else {
                float* Cf = (float*)Cv;
                *reinterpret_cast<float4*>(Cf + (size_t)m * 256 + n) = v;
            }
        }
    }
}

// ---------------- logits init: bb3 broadcast * 1/sqrt(d) -------------------
__global__ void k_initlog(const float* __restrict__ bb3,
                          float* __restrict__ logits) {
    int i = blockIdx.x * 256 + threadIdx.x;
    if (i < EE * NHD)
        logits[i] = __ldg(bb3 + (i & 7)) * 0.17677669529663687f;
}

// ---------------- index dtype sniff + normalize ----------------------------
__global__ void k_sniff(const int* __restrict__ buf) {
    __shared__ int nz;
    if (threadIdx.x == 0) nz = 0;
    __syncthreads();
    int w = buf[threadIdx.x * 2 + 1];
    if (w != 0) atomicOr(&nz, 1);
    __syncthreads();
    if (threadIdx.x == 0) g_is64 = nz ? 0 : 1;
}

__global__ void k_convert(const void* __restrict__ buf,
                          int* __restrict__ dst, int* __restrict__ src) {
    int e = blockIdx.x * 256 + threadIdx.x;
    if (e >= EE) return;
    if (g_is64) {
        const long long* p = (const long long*)buf;
        dst[e] = (int)p[e];
        src[e] = (int)p[EE + e];
    } else {
        const int* p = (const int*)buf;
        dst[e] = p[e];
        src[e] = p[EE + e];
    }
}

// ---------------- CSR build -------------------------------------------------
__global__ void k_zero(int* a, int* b, int n) {
    int i = blockIdx.x * blockDim.x + threadIdx.x;
    if (i < n) { a[i] = 0; b[i] = 0; }
}

__global__ void k_count(const int* __restrict__ dst, int* __restrict__ deg) {
    int e = blockIdx.x * 256 + threadIdx.x;
    if (e < EE) atomicAdd(&deg[dst[e]], 1);
}

__global__ void __launch_bounds__(1024) k_scan(
    const int* __restrict__ deg, int* __restrict__ off)
{
    __shared__ int ssum[1024];
    const int t = threadIdx.x;
    const int ITEMS = 10;
    int base = t * ITEMS;
    int loc[ITEMS];
    int s = 0;
#pragma unroll
    for (int i = 0; i < ITEMS; i++) {
        int v = (base + i < NN) ? deg[base + i] : 0;
        loc[i] = s;
        s += v;
    }
    ssum[t] = s;
    __syncthreads();
    for (int d = 1; d < 1024; d <<= 1) {
        int v = (t >= d) ? ssum[t - d] : 0;
        __syncthreads();
        if (t >= d) ssum[t] += v;
        __syncthreads();
    }
    int excl = (t == 0) ? 0 : ssum[t - 1];
#pragma unroll
    for (int i = 0; i < ITEMS; i++)
        if (base + i < NN) off[base + i] = excl + loc[i];
    if (t == 0) off[NN] = ssum[1023];
}

__global__ void k_fill(const int* __restrict__ dst,
                       const int* __restrict__ off, int* __restrict__ cur,
                       int* __restrict__ elist)
{
    int e = blockIdx.x * 256 + threadIdx.x;
    if (e < EE) {
        int d = dst[e];
        int p = off[d] + atomicAdd(&cur[d], 1);
        elist[p] = e;
    }
}

// ---------------- per-node softmax + weighted aggregation ------------------
__global__ void __launch_bounds__(256) k_softmax_agg(
    const float* __restrict__ logits, const float* __restrict__ V,
    const int* __restrict__ off, const int* __restrict__ elist,
    float* __restrict__ agg)
{
    int n = blockIdx.x;
    int tid = threadIdx.x;
    int lane = tid & 31;
    int w = tid >> 5;

    int s = off[n];
    int deg = off[n + 1] - s;
    if (deg == 0) { agg[(size_t)n * HH + tid] = 0.f; return; }

    __shared__ float s_m[NHD], s_d[NHD];
    __shared__ int s_eid[64];

    float mx = -INFINITY;
    for (int i = lane; i < deg; i += 32)
        mx = fmaxf(mx, logits[(size_t)elist[s + i] * NHD + w]);
#pragma unroll
    for (int o = 16; o; o >>= 1) mx = fmaxf(mx, __shfl_xor_sync(0xffffffffu, mx, o));
    float sum = 0.f;
    for (int i = lane; i < deg; i += 32)
        sum += expf(logits[(size_t)elist[s + i] * NHD + w] - mx);
#pragma unroll
    for (int o = 16; o; o >>= 1) sum += __shfl_xor_sync(0xffffffffu, sum, o);
    if (lane == 0) { s_m[w] = mx; s_d[w] = sum; }
    __syncthreads();

    float m_h = s_m[w];
    float inv_d = 1.0f / s_d[w];

    float acc = 0.f;
    for (int c0 = 0; c0 < deg; c0 += 64) {
        int len = min(64, deg - c0);
        __syncthreads();
        if (tid < len) s_eid[tid] = elist[s + c0 + tid];
        __syncthreads();
        float a0 = 0.f, a1 = 0.f;
        if (lane < len)
            a0 = expf(logits[(size_t)s_eid[lane] * NHD + w] - m_h) * inv_d;
        if (32 + lane < len)
            a1 = expf(logits[(size_t)s_eid[32 + lane] * NHD + w] - m_h) * inv_d;
        for (int i = 0; i < len; i++) {
            float av = (i < 32) ? a0 : a1;
            float att = __shfl_sync(0xffffffffu, av, i & 31);
            acc += att * __ldg(V + (size_t)s_eid[i] * HH + tid);
        }
    }
    agg[(size_t)n * HH + tid] = acc;
}

// ---------------- launch ----------------------------------------------------
extern "C" void kernel_launch(void* const* d_in, const int* in_sizes, int n_in,
                              void* d_out, int out_size)
{
    const float* src_na = (const float*)d_in[0];
    const float* dst_na = (const float*)d_in[1];
    const float* ea     = (const float*)d_in[2];
    const void*  eidx   = d_in[3];
    const float* Wv1 = (const float*)d_in[4];
    const float* bv1 = (const float*)d_in[5];
    const float* Wv2 = (const float*)d_in[6];
    const float* bv2 = (const float*)d_in[7];
    const float* Wv3 = (const float*)d_in[8];
    const float* bv3 = (const float*)d_in[9];
    const float* Wb1 = (const float*)d_in[10];
    const float* bb1 = (const float*)d_in[11];
    const float* Wb2 = (const float*)d_in[12];
    const float* bb2 = (const float*)d_in[13];
    const float* Wb3 = (const float*)d_in[14];
    const float* bb3 = (const float*)d_in[15];
    const float* WO  = (const float*)d_in[16];

    float *pS1, *pT1, *pSv, *pe1, *pe2, *plog, *pagg;
    int *pdeg, *pcur, *poff, *pel, *pdst, *psrc;
    cudaGetSymbolAddress((void**)&pS1, g_S1);
    cudaGetSymbolAddress((void**)&pT1, g_T1);
    cudaGetSymbolAddress((void**)&pSv, g_Sv);
    cudaGetSymbolAddress((void**)&pe1, g_e1);
    cudaGetSymbolAddress((void**)&pe2, g_e2);
    cudaGetSymbolAddress((void**)&plog, g_logits);
    cudaGetSymbolAddress((void**)&pagg, g_agg);
    cudaGetSymbolAddress((void**)&pdeg, g_deg);
    cudaGetSymbolAddress((void**)&pcur, g_cur);
    cudaGetSymbolAddress((void**)&poff, g_off);
    cudaGetSymbolAddress((void**)&pel, g_elist);
    cudaGetSymbolAddress((void**)&pdst, g_dst);
    cudaGetSymbolAddress((void**)&psrc, g_src);

    cudaFuncSetAttribute(mma_gemm<false, false>,
        cudaFuncAttributeMaxDynamicSharedMemorySize, SMEM_BYTES);
    cudaFuncSetAttribute(mma_gemm<false, true>,
        cudaFuncAttributeMaxDynamicSharedMemorySize, SMEM_BYTES);
    cudaFuncSetAttribute(mma_gemm<true, false>,
        cudaFuncAttributeMaxDynamicSharedMemorySize, SMEM_BYTES);
    cudaFuncSetAttribute(mma_gemm<true, true>,
        cudaFuncAttributeMaxDynamicSharedMemorySize, SMEM_BYTES);

    dim3 gn((NN + 127) / 128, 2);   // 79 x 2
    dim3 ge(EE / 128, 2);           // 2500 x 2

    // 1-2: index normalize
    k_sniff<<<1, 128>>>((const int*)eidx);
    k_convert<<<(EE + 255) / 256, 256>>>(eidx, pdst, psrc);

    // 3-5: node precomputes (fp32 in/out -- consumed as epilogue adds)
    mma_gemm<false, false><<<gn, 256, SMEM_BYTES>>>(src_na, 256, Wb1, 768,
        nullptr, nullptr, nullptr, nullptr, nullptr, pS1, NN, 0, nullptr, nullptr);
    mma_gemm<false, false><<<gn, 256, SMEM_BYTES>>>(dst_na, 256, Wb1 + 512, 768,
        nullptr, nullptr, nullptr, nullptr, nullptr, pT1, NN, 0, nullptr, nullptr);
    mma_gemm<false, false><<<gn, 256, SMEM_BYTES>>>(src_na, 256, Wv1, 512,
        nullptr, nullptr, nullptr, nullptr, nullptr, pSv, NN, 0, nullptr, nullptr);

    // 6: h1 = relu(ea@Wb1_e^T + S1[src] + T1[dst] + bb1) -> fp16 pe1
    mma_gemm<false, true><<<ge, 256, SMEM_BYTES>>>(ea, 256, Wb1 + 256, 768, bb1,
        pS1, psrc, pT1, pdst, pe1, EE, 1, nullptr, nullptr);

    // 7-8: logits init, fused h2+logits (A = fp16 h1; h2 never materialized)
    k_initlog<<<(EE * NHD) / 256, 256>>>(bb3, plog);
    mma_gemm<true, false><<<ge, 256, SMEM_BYTES>>>(pe1, 256, Wb2, 256, bb2,
        nullptr, nullptr, nullptr, nullptr, nullptr, EE, 3, Wb3, plog);

    // 9: v1 = gelu(ea@Wv1_e^T + Sv[src] + bv1) -> fp16 pe2
    mma_gemm<false, true><<<ge, 256, SMEM_BYTES>>>(ea, 256, Wv1 + 256, 512, bv1,
        pSv, psrc, nullptr, nullptr, pe2, EE, 2, nullptr, nullptr);

    // 10-13: CSR build
    k_zero<<<(NN + 255) / 256, 256>>>(pdeg, pcur, NN);
    k_count<<<EE / 256, 256>>>(pdst, pdeg);
    k_scan<<<1, 1024>>>(pdeg, poff);
    k_fill<<<EE / 256, 256>>>(pdst, poff, pcur, pel);

    // 14: v2 = gelu(v1@Wv2^T + bv2)  fp16 -> fp16 pe1
    mma_gemm<true, true><<<ge, 256, SMEM_BYTES>>>(pe2, 256, Wv2, 256, bv2,
        nullptr, nullptr, nullptr, nullptr, pe1, EE, 2, nullptr, nullptr);
    // 15: V = v2@Wv3^T + bv3  fp16 -> fp32 pe2 (consumed by softmax_agg)
    mma_gemm<true, false><<<ge, 256, SMEM_BYTES>>>(pe1, 256, Wv3, 256, bv3,
        nullptr, nullptr, nullptr, nullptr, pe2, EE, 0, nullptr, nullptr);

    // 16: per-node softmax + aggregation
    k_softmax_agg<<<NN, 256>>>(plog, pe2, poff, pel, pagg);

    // 17: output projection (fp32 in/out)
    mma_gemm<false, false><<<gn, 256, SMEM_BYTES>>>(pagg, 256, WO, 256, nullptr,
        nullptr, nullptr, nullptr, nullptr, (float*)d_out, NN, 0,
        nullptr, nullptr);
}

// round 15
// speedup vs baseline: 1.6525x; 1.0022x over previous
#include <cuda_runtime.h>
#include <cuda_bf16.h>
#include <cuda_fp16.h>
#include <stdint.h>
#include <math.h>

#define NN 10000
#define EE 320000
#define HH 256
#define NHD 8

// ---------------- scratch (static device globals; no runtime alloc) --------
__device__ float g_S1[NN * HH];
__device__ float g_T1[NN * HH];
__device__ float g_Sv[NN * HH];
__device__ float g_e1[(size_t)EE * HH];   // used as half or float per stage
__device__ float g_e2[(size_t)EE * HH];
__device__ float g_logits[(size_t)EE * NHD];
__device__ float g_agg[NN * HH];
__device__ int   g_deg[NN];
__device__ int   g_cur[NN];
__device__ int   g_off[NN + 1];
__device__ int   g_elist[EE];
__device__ int   g_dst[EE];
__device__ int   g_src[EE];
__device__ int   g_is64;

__device__ __forceinline__ float gelu_f(float x) {
    return 0.5f * x * (1.0f + erff(x * 0.7071067811865476f));
}

__device__ __forceinline__ unsigned int pack_h2(float lo, float hi) {
    __half2 h = __floats2half2_rn(lo, hi);
    return *reinterpret_cast<unsigned int*>(&h);
}

// m16n8k16 fp16 mma (row.col), fp32 accumulate
__device__ __forceinline__ void mma_f16(float* c, const unsigned int* a,
                                        const unsigned int* b) {
    asm volatile(
        "mma.sync.aligned.m16n8k16.row.col.f32.f16.f16.f32 "
        "{%0,%1,%2,%3}, {%4,%5,%6,%7}, {%8,%9}, {%0,%1,%2,%3};"
        : "+f"(c[0]), "+f"(c[1]), "+f"(c[2]), "+f"(c[3])
        : "r"(a[0]), "r"(a[1]), "r"(a[2]), "r"(a[3]), "r"(b[0]), "r"(b[1]));
}

__device__ __forceinline__ unsigned int smem_u32(const void* p) {
    unsigned int a;
    asm("{ .reg .u64 t; cvta.to.shared.u64 t, %1; cvt.u32.u64 %0, t; }"
        : "=r"(a) : "l"(p));
    return a;
}

__device__ __forceinline__ void ldsm_x4(unsigned int* r, unsigned int addr) {
    asm volatile(
        "ldmatrix.sync.aligned.m8n8.x4.shared.b16 {%0,%1,%2,%3}, [%4];"
        : "=r"(r[0]), "=r"(r[1]), "=r"(r[2]), "=r"(r[3]) : "r"(addr));
}
__device__ __forceinline__ void ldsm_x2(unsigned int* r, unsigned int addr) {
    asm volatile(
        "ldmatrix.sync.aligned.m8n8.x2.shared.b16 {%0,%1}, [%2];"
        : "=r"(r[0]), "=r"(r[1]) : "r"(addr));
}

// ---------------- fp16 mma.sync GEMM: C = act(A @ W^T + bias + gathers) ----
// AHALF: A is fp16 (direct STS, no cvt). CHALF: C written as fp16.
// CTA tile 128 x 128 (grid.y over 2 N-halves). K=256, 8 dbl-buffered chunks.
// act: 0 none, 1 relu, 2 gelu, 3 relu + fused logits projection (no C write)
#define HSTR 40                        // halves per smem row (32 + 8 pad)
#define BUF_H (128 * HSTR)             // 5120 halves = 10240 B per buffer
#define BUF_B (BUF_H * 2)
#define SMEM_BYTES 73728               // 4 bufs (40960) + epilogue stage reuse

template <bool AHALF, bool CHALF>
__global__ void __launch_bounds__(256, 2) mma_gemm(
    const void* __restrict__ Av, int lda,
    const float* __restrict__ W, int ldw,
    const float* __restrict__ bias,
    const float* __restrict__ add1, const int* __restrict__ idx1,
    const float* __restrict__ add2, const int* __restrict__ idx2,
    void* __restrict__ Cv, int M, int act,
    const float* __restrict__ Wb3, float* __restrict__ logits)
{
    extern __shared__ float smf[];
    unsigned int* smw = reinterpret_cast<unsigned int*>(smf);
    char* smc = reinterpret_cast<char*>(smf);
    const unsigned int smb = smem_u32(smf);

    const int tid = threadIdx.x;
    const int wid = tid >> 5;
    const int lane = tid & 31;
    const int warp_m = wid & 1;
    const int warp_n = wid >> 1;
    const int qr = lane >> 2;
    const int qc = lane & 3;
    const int m0 = blockIdx.x * 128;
    const int n0 = blockIdx.y * 128;

    // ldmatrix per-lane byte-offset constants (layout proven in R13)
    const int lm = lane >> 3;
    const int lr8 = lane & 7;
    const int a_lane_b = (warp_m * 64 + ((lm & 1) << 3) + lr8) * 80
                       + (((lm >> 1) << 3) << 1);
    const int blm = (lane & 15) >> 3;
    const int b_lane_b = (warp_n * 32 + lr8) * 80 + (blm << 4);

    float c[4][4][4];
#pragma unroll
    for (int i = 0; i < 4; i++)
#pragma unroll
        for (int j = 0; j < 4; j++)
#pragma unroll
            for (int q = 0; q < 4; q++) c[i][j][q] = 0.f;

    float4 ra[4], rb[4];
    uint4 ha[2];

    auto load_regs = [&](int kc) {
        const int kcol = kc * 32;
        if (AHALF) {
            const __half* Ah = (const __half*)Av;
#pragma unroll
            for (int it = 0; it < 2; it++) {
                int idx = tid + it * 256;
                int r = idx >> 2, q = idx & 3;
                ha[it] = make_uint4(0u, 0u, 0u, 0u);
                if (m0 + r < M)
                    ha[it] = *reinterpret_cast<const uint4*>(
                        Ah + (size_t)(m0 + r) * lda + kcol + q * 8);
            }
        } else {
            const float* Af = (const float*)Av;
#pragma unroll
            for (int it = 0; it < 4; it++) {
                int idx = tid + it * 256;
                int r = idx >> 3, f4 = idx & 7;
                ra[it] = make_float4(0.f, 0.f, 0.f, 0.f);
                if (m0 + r < M)
                    ra[it] = *reinterpret_cast<const float4*>(
                        Af + (size_t)(m0 + r) * lda + kcol + f4 * 4);
            }
        }
#pragma unroll
        for (int it = 0; it < 4; it++) {
            int idx = tid + it * 256;
            int r = idx >> 3, f4 = idx & 7;
            rb[it] = *reinterpret_cast<const float4*>(
                W + (size_t)(n0 + r) * ldw + kcol + f4 * 4);
        }
    };
    auto store_regs = [&](int buf) {
        if (AHALF) {
            char* sA = smc + buf * BUF_B;
#pragma unroll
            for (int it = 0; it < 2; it++) {
                int idx = tid + it * 256;
                int r = idx >> 2, q = idx & 3;
                *reinterpret_cast<uint4*>(sA + r * 80 + q * 16) = ha[it];
            }
        } else {
            unsigned int* sA = smw + buf * (BUF_B / 4);
#pragma unroll
            for (int it = 0; it < 4; it++) {
                int idx = tid + it * 256;
                int r = idx >> 3, f4 = idx & 7;
                uint2 ta;
                ta.x = pack_h2(ra[it].x, ra[it].y);
                ta.y = pack_h2(ra[it].z, ra[it].w);
                *reinterpret_cast<uint2*>(sA + r * 20 + f4 * 2) = ta;
            }
        }
        unsigned int* sB = smw + (2 + buf) * (BUF_B / 4);
#pragma unroll
        for (int it = 0; it < 4; it++) {
            int idx = tid + it * 256;
            int r = idx >> 3, f4 = idx & 7;
            uint2 tb;
            tb.x = pack_h2(rb[it].x, rb[it].y);
            tb.y = pack_h2(rb[it].z, rb[it].w);
            *reinterpret_cast<uint2*>(sB + r * 20 + f4 * 2) = tb;
        }
    };
    auto mma_k = [&](int b, int ks) {
        const unsigned int baseA = smb + b * BUF_B;
        const unsigned int baseB = smb + (2 + b) * BUF_B;
        unsigned int af[4][4], bf[4][2];
#pragma unroll
        for (int mt = 0; mt < 4; mt++)
            ldsm_x4(af[mt],
                    baseA + (unsigned)(a_lane_b + mt * 1280 + ks * 32));
#pragma unroll
        for (int nt = 0; nt < 4; nt++)
            ldsm_x2(bf[nt],
                    baseB + (unsigned)(b_lane_b + nt * 640 + ks * 32));
#pragma unroll
        for (int mt = 0; mt < 4; mt++)
#pragma unroll
            for (int nt = 0; nt < 4; nt++)
                mma_f16(c[mt][nt], af[mt], bf[nt]);
    };

    load_regs(0);
    store_regs(0);
    __syncthreads();

#pragma unroll 1
    for (int kc = 0; kc < 8; kc++) {
        const int b = kc & 1;
        if (kc < 7) load_regs(kc + 1);     // LDGs in flight during MMAs
        mma_k(b, 0);
        if (kc < 7) store_regs(b ^ 1);     // cvt+STS after latency covered
        mma_k(b, 1);
        __syncthreads();
    }

    // ---- stage accumulators in smem (128 x 132) ----
    float* stage = smf;
#pragma unroll
    for (int mt = 0; mt < 4; mt++) {
#pragma unroll
        for (int nt = 0; nt < 4; nt++) {
            int row = warp_m * 64 + mt * 16 + qr;
            int col = warp_n * 32 + nt * 8 + qc * 2;
            *reinterpret_cast<float2*>(stage + row * 132 + col) =
                make_float2(c[mt][nt][0], c[mt][nt][1]);
            *reinterpret_cast<float2*>(stage + (row + 8) * 132 + col) =
                make_float2(c[mt][nt][2], c[mt][nt][3]);
        }
    }
    __syncthreads();

    if (act == 3) {
        // fused logits: logits[m][h] += sum_n relu(h2_mn) * Wb3[h][n]/sqrt(d)
        float* sW3 = smf + 128 * 132;          // 8 x 128
        float* sb = sW3 + 1024;                // 128
        for (int i = tid; i < 1024; i += 256)
            sW3[i] = Wb3[(i >> 7) * 256 + n0 + (i & 127)];
        if (tid < 128) sb[tid] = bias[n0 + tid];
        __syncthreads();

        int row = tid >> 1, half = tid & 1;
        int m = m0 + row;
        float acc[NHD];
#pragma unroll
        for (int h = 0; h < NHD; h++) acc[h] = 0.f;
        const float* srow = smf + row * 132 + half * 64;
        const float* brow = sb + half * 64;
        const float* wrow = sW3 + half * 64;
#pragma unroll 8
        for (int cc = 0; cc < 64; cc++) {
            float v = fmaxf(srow[cc] + brow[cc], 0.f);
#pragma unroll
            for (int h = 0; h < NHD; h++) acc[h] += v * wrow[h * 128 + cc];
        }
#pragma unroll
        for (int h = 0; h < NHD; h++)
            atomicAdd(&logits[(size_t)m * NHD + h],
                      acc[h] * 0.17677669529663687f);
        return;
    }

    // ---- fused epilogue, coalesced (float4 or half2x2) ----
#pragma unroll 4
    for (int i = 0; i < 16; i++) {
        int idx = i * 256 + tid;
        int row = idx >> 5;
        int col = (idx & 31) * 4;
        int m = m0 + row, n = n0 + col;
        if (m < M) {
            float4 v = *reinterpret_cast<float4*>(stage + row * 132 + col);
            if (bias) {
                float4 bv = *reinterpret_cast<const float4*>(bias + n);
                v.x += bv.x; v.y += bv.y; v.z += bv.z; v.w += bv.w;
            }
            if (add1) {
                float4 a = *reinterpret_cast<const float4*>(
                    add1 + (size_t)idx1[m] * 256 + n);
                v.x += a.x; v.y += a.y; v.z += a.z; v.w += a.w;
            }
            if (add2) {
                float4 a = *reinterpret_cast<const float4*>(
                    add2 + (size_t)idx2[m] * 256 + n);
                v.x += a.x; v.y += a.y; v.z += a.z; v.w += a.w;
            }
            if (act == 1) {
                v.x = fmaxf(v.x, 0.f); v.y = fmaxf(v.y, 0.f);
                v.z = fmaxf(v.z, 0.f); v.w = fmaxf(v.w, 0.f);
            } else if (act == 2) {
                v.x = gelu_f(v.x); v.y = gelu_f(v.y);
                v.z = gelu_f(v.z); v.w = gelu_f(v.w);
            }
            if (CHALF) {
                __half* Ch = (__half*)Cv;
                uint2 o;
                o.x = pack_h2(v.x, v.y);
                o.y = pack_h2(v.z, v.w);
                *reinterpret_cast<uint2*>(Ch + (size_t)m * 256 + n) = o;
            } else {
                float* Cf = (float*)Cv;
                *reinterpret_cast<float4*>(Cf + (size_t)m * 256 + n) = v;
            }
        }
    }
}

// ---------------- logits init: bb3 broadcast * 1/sqrt(d) -------------------
__global__ void k_initlog(const float* __restrict__ bb3,
                          float* __restrict__ logits) {
    int i = blockIdx.x * 256 + threadIdx.x;
    if (i < EE * NHD)
        logits[i] = __ldg(bb3 + (i & 7)) * 0.17677669529663687f;
}

// ---------------- index dtype sniff + normalize ----------------------------
__global__ void k_sniff(const int* __restrict__ buf) {
    __shared__ int nz;
    if (threadIdx.x == 0) nz = 0;
    __syncthreads();
    int w = buf[threadIdx.x * 2 + 1];
    if (w != 0) atomicOr(&nz, 1);
    __syncthreads();
    if (threadIdx.x == 0) g_is64 = nz ? 0 : 1;
}

__global__ void k_convert(const void* __restrict__ buf,
                          int* __restrict__ dst, int* __restrict__ src) {
    int e = blockIdx.x * 256 + threadIdx.x;
    if (e >= EE) return;
    if (g_is64) {
        const long long* p = (const long long*)buf;
        dst[e] = (int)p[e];
        src[e] = (int)p[EE + e];
    } else {
        const int* p = (const int*)buf;
        dst[e] = p[e];
        src[e] = p[EE + e];
    }
}

// ---------------- CSR build -------------------------------------------------
__global__ void k_zero(int* a, int* b, int n) {
    int i = blockIdx.x * blockDim.x + threadIdx.x;
    if (i < n) { a[i] = 0; b[i] = 0; }
}

__global__ void k_count(const int* __restrict__ dst, int* __restrict__ deg) {
    int e = blockIdx.x * 256 + threadIdx.x;
    if (e < EE) atomicAdd(&deg[dst[e]], 1);
}

__global__ void __launch_bounds__(1024) k_scan(
    const int* __restrict__ deg, int* __restrict__ off)
{
    __shared__ int ssum[1024];
    const int t = threadIdx.x;
    const int ITEMS = 10;
    int base = t * ITEMS;
    int loc[ITEMS];
    int s = 0;
#pragma unroll
    for (int i = 0; i < ITEMS; i++) {
        int v = (base + i < NN) ? deg[base + i] : 0;
        loc[i] = s;
        s += v;
    }
    ssum[t] = s;
    __syncthreads();
    for (int d = 1; d < 1024; d <<= 1) {
        int v = (t >= d) ? ssum[t - d] : 0;
        __syncthreads();
        if (t >= d) ssum[t] += v;
        __syncthreads();
    }
    int excl = (t == 0) ? 0 : ssum[t - 1];
#pragma unroll
    for (int i = 0; i < ITEMS; i++)
        if (base + i < NN) off[base + i] = excl + loc[i];
    if (t == 0) off[NN] = ssum[1023];
}

__global__ void k_fill(const int* __restrict__ dst,
                       const int* __restrict__ off, int* __restrict__ cur,
                       int* __restrict__ elist)
{
    int e = blockIdx.x * 256 + threadIdx.x;
    if (e < EE) {
        int d = dst[e];
        int p = off[d] + atomicAdd(&cur[d], 1);
        elist[p] = e;
    }
}

// ---------------- per-node softmax + weighted aggregation ------------------
__global__ void __launch_bounds__(256) k_softmax_agg(
    const float* __restrict__ logits, const float* __restrict__ V,
    const int* __restrict__ off, const int* __restrict__ elist,
    float* __restrict__ agg)
{
    int n = blockIdx.x;
    int tid = threadIdx.x;
    int lane = tid & 31;
    int w = tid >> 5;

    int s = off[n];
    int deg = off[n + 1] - s;
    if (deg == 0) { agg[(size_t)n * HH + tid] = 0.f; return; }

    __shared__ float s_m[NHD], s_d[NHD];
    __shared__ int s_eid[64];

    float mx = -INFINITY;
    for (int i = lane; i < deg; i += 32)
        mx = fmaxf(mx, logits[(size_t)elist[s + i] * NHD + w]);
#pragma unroll
    for (int o = 16; o; o >>= 1) mx = fmaxf(mx, __shfl_xor_sync(0xffffffffu, mx, o));
    float sum = 0.f;
    for (int i = lane; i < deg; i += 32)
        sum += expf(logits[(size_t)elist[s + i] * NHD + w] - mx);
#pragma unroll
    for (int o = 16; o; o >>= 1) sum += __shfl_xor_sync(0xffffffffu, sum, o);
    if (lane == 0) { s_m[w] = mx; s_d[w] = sum; }
    __syncthreads();

    float m_h = s_m[w];
    float inv_d = 1.0f / s_d[w];

    float acc = 0.f;
    for (int c0 = 0; c0 < deg; c0 += 64) {
        int len = min(64, deg - c0);
        __syncthreads();
        if (tid < len) s_eid[tid] = elist[s + c0 + tid];
        __syncthreads();
        float a0 = 0.f, a1 = 0.f;
        if (lane < len)
            a0 = expf(logits[(size_t)s_eid[lane] * NHD + w] - m_h) * inv_d;
        if (32 + lane < len)
            a1 = expf(logits[(size_t)s_eid[32 + lane] * NHD + w] - m_h) * inv_d;
        for (int i = 0; i < len; i++) {
            float av = (i < 32) ? a0 : a1;
            float att = __shfl_sync(0xffffffffu, av, i & 31);
            acc += att * __ldg(V + (size_t)s_eid[i] * HH + tid);
        }
    }
    agg[(size_t)n * HH + tid] = acc;
}

// ---------------- launch ----------------------------------------------------
extern "C" void kernel_launch(void* const* d_in, const int* in_sizes, int n_in,
                              void* d_out, int out_size)
{
    const float* src_na = (const float*)d_in[0];
    const float* dst_na = (const float*)d_in[1];
    const float* ea     = (const float*)d_in[2];
    const void*  eidx   = d_in[3];
    const float* Wv1 = (const float*)d_in[4];
    const float* bv1 = (const float*)d_in[5];
    const float* Wv2 = (const float*)d_in[6];
    const float* bv2 = (const float*)d_in[7];
    const float* Wv3 = (const float*)d_in[8];
    const float* bv3 = (const float*)d_in[9];
    const float* Wb1 = (const float*)d_in[10];
    const float* bb1 = (const float*)d_in[11];
    const float* Wb2 = (const float*)d_in[12];
    const float* bb2 = (const float*)d_in[13];
    const float* Wb3 = (const float*)d_in[14];
    const float* bb3 = (const float*)d_in[15];
    const float* WO  = (const float*)d_in[16];

    float *pS1, *pT1, *pSv, *pe1, *pe2, *plog, *pagg;
    int *pdeg, *pcur, *poff, *pel, *pdst, *psrc;
    cudaGetSymbolAddress((void**)&pS1, g_S1);
    cudaGetSymbolAddress((void**)&pT1, g_T1);
    cudaGetSymbolAddress((void**)&pSv, g_Sv);
    cudaGetSymbolAddress((void**)&pe1, g_e1);
    cudaGetSymbolAddress((void**)&pe2, g_e2);
    cudaGetSymbolAddress((void**)&plog, g_logits);
    cudaGetSymbolAddress((void**)&pagg, g_agg);
    cudaGetSymbolAddress((void**)&pdeg, g_deg);
    cudaGetSymbolAddress((void**)&pcur, g_cur);
    cudaGetSymbolAddress((void**)&poff, g_off);
    cudaGetSymbolAddress((void**)&pel, g_elist);
    cudaGetSymbolAddress((void**)&pdst, g_dst);
    cudaGetSymbolAddress((void**)&psrc, g_src);

    cudaFuncSetAttribute(mma_gemm<false, false>,
        cudaFuncAttributeMaxDynamicSharedMemorySize, SMEM_BYTES);
    cudaFuncSetAttribute(mma_gemm<false, true>,
        cudaFuncAttributeMaxDynamicSharedMemorySize, SMEM_BYTES);
    cudaFuncSetAttribute(mma_gemm<true, false>,
        cudaFuncAttributeMaxDynamicSharedMemorySize, SMEM_BYTES);
    cudaFuncSetAttribute(mma_gemm<true, true>,
        cudaFuncAttributeMaxDynamicSharedMemorySize, SMEM_BYTES);

    dim3 gn((NN + 127) / 128, 2);   // 79 x 2
    dim3 ge(EE / 128, 2);           // 2500 x 2

    // 1-2: index normalize
    k_sniff<<<1, 128>>>((const int*)eidx);
    k_convert<<<(EE + 255) / 256, 256>>>(eidx, pdst, psrc);

    // 3-5: node precomputes (fp32 in/out -- consumed as epilogue adds)
    mma_gemm<false, false><<<gn, 256, SMEM_BYTES>>>(src_na, 256, Wb1, 768,
        nullptr, nullptr, nullptr, nullptr, nullptr, pS1, NN, 0, nullptr, nullptr);
    mma_gemm<false, false><<<gn, 256, SMEM_BYTES>>>(dst_na, 256, Wb1 + 512, 768,
        nullptr, nullptr, nullptr, nullptr, nullptr, pT1, NN, 0, nullptr, nullptr);
    mma_gemm<false, false><<<gn, 256, SMEM_BYTES>>>(src_na, 256, Wv1, 512,
        nullptr, nullptr, nullptr, nullptr, nullptr, pSv, NN, 0, nullptr, nullptr);

    // 6: h1 = relu(ea@Wb1_e^T + S1[src] + T1[dst] + bb1) -> fp16 pe1
    mma_gemm<false, true><<<ge, 256, SMEM_BYTES>>>(ea, 256, Wb1 + 256, 768, bb1,
        pS1, psrc, pT1, pdst, pe1, EE, 1, nullptr, nullptr);

    // 7-8: logits init, fused h2+logits (A = fp16 h1; h2 never materialized)
    k_initlog<<<(EE * NHD) / 256, 256>>>(bb3, plog);
    mma_gemm<true, false><<<ge, 256, SMEM_BYTES>>>(pe1, 256, Wb2, 256, bb2,
        nullptr, nullptr, nullptr, nullptr, nullptr, EE, 3, Wb3, plog);

    // 9: v1 = gelu(ea@Wv1_e^T + Sv[src] + bv1) -> fp16 pe2
    mma_gemm<false, true><<<ge, 256, SMEM_BYTES>>>(ea, 256, Wv1 + 256, 512, bv1,
        pSv, psrc, nullptr, nullptr, pe2, EE, 2, nullptr, nullptr);

    // 10-13: CSR build
    k_zero<<<(NN + 255) / 256, 256>>>(pdeg, pcur, NN);
    k_count<<<EE / 256, 256>>>(pdst, pdeg);
    k_scan<<<1, 1024>>>(pdeg, poff);
    k_fill<<<EE / 256, 256>>>(pdst, poff, pcur, pel);

    // 14: v2 = gelu(v1@Wv2^T + bv2)  fp16 -> fp16 pe1
    mma_gemm<true, true><<<ge, 256, SMEM_BYTES>>>(pe2, 256, Wv2, 256, bv2,
        nullptr, nullptr, nullptr, nullptr, pe1, EE, 2, nullptr, nullptr);
    // 15: V = v2@Wv3^T + bv3  fp16 -> fp32 pe2 (consumed by softmax_agg)
    mma_gemm<true, false><<<ge, 256, SMEM_BYTES>>>(pe1, 256, Wv3, 256, bv3,
        nullptr, nullptr, nullptr, nullptr, pe2, EE, 0, nullptr, nullptr);

    // 16: per-node softmax + aggregation
    k_softmax_agg<<<NN, 256>>>(plog, pe2, poff, pel, pagg);

    // 17: output projection (fp32 in/out)
    mma_gemm<false, false><<<gn, 256, SMEM_BYTES>>>(pagg, 256, WO, 256, nullptr,
        nullptr, nullptr, nullptr, nullptr, (float*)d_out, NN, 0,
        nullptr, nullptr);
}

// round 16
// speedup vs baseline: 1.7510x; 1.0596x over previous
#include <cuda_runtime.h>
#include <cuda_bf16.h>
#include <cuda_fp16.h>
#include <stdint.h>
#include <math.h>

#define NN 10000
#define EE 320000
#define HH 256
#define NHD 8

// ---------------- scratch (static device globals; no runtime alloc) --------
__device__ float g_S1[NN * HH];
__device__ float g_T1[NN * HH];
__device__ float g_Sv[NN * HH];
__device__ float g_e1[(size_t)EE * HH];   // used as half or float per stage
__device__ float g_e2[(size_t)EE * HH];
__device__ float g_logits[(size_t)EE * NHD];
__device__ float g_agg[NN * HH];
__device__ int   g_deg[NN];
__device__ int   g_cur[NN];
__device__ int   g_off[NN + 1];
__device__ int   g_elist[EE];
__device__ int   g_dst[EE];
__device__ int   g_src[EE];
__device__ int   g_is64;

__device__ __forceinline__ float gelu_f(float x) {
    return 0.5f * x * (1.0f + erff(x * 0.7071067811865476f));
}

__device__ __forceinline__ unsigned int pack_h2(float lo, float hi) {
    __half2 h = __floats2half2_rn(lo, hi);
    return *reinterpret_cast<unsigned int*>(&h);
}

// m16n8k16 fp16 mma (row.col), fp32 accumulate
__device__ __forceinline__ void mma_f16(float* c, const unsigned int* a,
                                        const unsigned int* b) {
    asm volatile(
        "mma.sync.aligned.m16n8k16.row.col.f32.f16.f16.f32 "
        "{%0,%1,%2,%3}, {%4,%5,%6,%7}, {%8,%9}, {%0,%1,%2,%3};"
        : "+f"(c[0]), "+f"(c[1]), "+f"(c[2]), "+f"(c[3])
        : "r"(a[0]), "r"(a[1]), "r"(a[2]), "r"(a[3]), "r"(b[0]), "r"(b[1]));
}

__device__ __forceinline__ unsigned int smem_u32(const void* p) {
    unsigned int a;
    asm("{ .reg .u64 t; cvta.to.shared.u64 t, %1; cvt.u32.u64 %0, t; }"
        : "=r"(a) : "l"(p));
    return a;
}

__device__ __forceinline__ void ldsm_x4(unsigned int* r, unsigned int addr) {
    asm volatile(
        "ldmatrix.sync.aligned.m8n8.x4.shared.b16 {%0,%1,%2,%3}, [%4];"
        : "=r"(r[0]), "=r"(r[1]), "=r"(r[2]), "=r"(r[3]) : "r"(addr));
}
__device__ __forceinline__ void ldsm_x2(unsigned int* r, unsigned int addr) {
    asm volatile(
        "ldmatrix.sync.aligned.m8n8.x2.shared.b16 {%0,%1}, [%2];"
        : "=r"(r[0]), "=r"(r[1]) : "r"(addr));
}

// ---------------- fp16 mma.sync GEMM: C = act(A @ W^T + bias + gathers) ----
// AHALF: A is fp16 (direct STS, no cvt). CHALF: C written as fp16.
// CTA tile 128 x 128 (grid.y over 2 N-halves). K=256, 8 dbl-buffered chunks.
// act: 0 none, 1 relu, 2 gelu, 3 relu + fused logits projection (no C write)
#define HSTR 40                        // halves per smem row (32 + 8 pad)
#define BUF_H (128 * HSTR)             // 5120 halves = 10240 B per buffer
#define BUF_B (BUF_H * 2)
#define SMEM_BYTES 73728               // 4 bufs (40960) + epilogue stage reuse

template <bool AHALF, bool CHALF>
__global__ void __launch_bounds__(256, 2) mma_gemm(
    const void* __restrict__ Av, int lda,
    const float* __restrict__ W, int ldw,
    const float* __restrict__ bias,
    const float* __restrict__ add1, const int* __restrict__ idx1,
    const float* __restrict__ add2, const int* __restrict__ idx2,
    void* __restrict__ Cv, int M, int act,
    const float* __restrict__ Wb3, float* __restrict__ logits)
{
    extern __shared__ float smf[];
    unsigned int* smw = reinterpret_cast<unsigned int*>(smf);
    char* smc = reinterpret_cast<char*>(smf);
    const unsigned int smb = smem_u32(smf);

    const int tid = threadIdx.x;
    const int wid = tid >> 5;
    const int lane = tid & 31;
    const int warp_m = wid & 1;
    const int warp_n = wid >> 1;
    const int qr = lane >> 2;
    const int qc = lane & 3;
    const int m0 = blockIdx.x * 128;
    const int n0 = blockIdx.y * 128;

    // ldmatrix per-lane byte-offset constants (layout proven in R13)
    const int lm = lane >> 3;
    const int lr8 = lane & 7;
    const int a_lane_b = (warp_m * 64 + ((lm & 1) << 3) + lr8) * 80
                       + (((lm >> 1) << 3) << 1);
    const int blm = (lane & 15) >> 3;
    const int b_lane_b = (warp_n * 32 + lr8) * 80 + (blm << 4);

    float c[4][4][4];
#pragma unroll
    for (int i = 0; i < 4; i++)
#pragma unroll
        for (int j = 0; j < 4; j++)
#pragma unroll
            for (int q = 0; q < 4; q++) c[i][j][q] = 0.f;

    float4 ra[4], rb[4];
    uint4 ha[2];

    auto load_regs = [&](int kc) {
        const int kcol = kc * 32;
        if (AHALF) {
            const __half* Ah = (const __half*)Av;
#pragma unroll
            for (int it = 0; it < 2; it++) {
                int idx = tid + it * 256;
                int r = idx >> 2, q = idx & 3;
                ha[it] = make_uint4(0u, 0u, 0u, 0u);
                if (m0 + r < M)
                    ha[it] = *reinterpret_cast<const uint4*>(
                        Ah + (size_t)(m0 + r) * lda + kcol + q * 8);
            }
        } else {
            const float* Af = (const float*)Av;
#pragma unroll
            for (int it = 0; it < 4; it++) {
                int idx = tid + it * 256;
                int r = idx >> 3, f4 = idx & 7;
                ra[it] = make_float4(0.f, 0.f, 0.f, 0.f);
                if (m0 + r < M)
                    ra[it] = *reinterpret_cast<const float4*>(
                        Af + (size_t)(m0 + r) * lda + kcol + f4 * 4);
            }
        }
#pragma unroll
        for (int it = 0; it < 4; it++) {
            int idx = tid + it * 256;
            int r = idx >> 3, f4 = idx & 7;
            rb[it] = *reinterpret_cast<const float4*>(
                W + (size_t)(n0 + r) * ldw + kcol + f4 * 4);
        }
    };
    auto store_regs = [&](int buf) {
        if (AHALF) {
            char* sA = smc + buf * BUF_B;
#pragma unroll
            for (int it = 0; it < 2; it++) {
                int idx = tid + it * 256;
                int r = idx >> 2, q = idx & 3;
                *reinterpret_cast<uint4*>(sA + r * 80 + q * 16) = ha[it];
            }
        } else {
            unsigned int* sA = smw + buf * (BUF_B / 4);
#pragma unroll
            for (int it = 0; it < 4; it++) {
                int idx = tid + it * 256;
                int r = idx >> 3, f4 = idx & 7;
                uint2 ta;
                ta.x = pack_h2(ra[it].x, ra[it].y);
                ta.y = pack_h2(ra[it].z, ra[it].w);
                *reinterpret_cast<uint2*>(sA + r * 20 + f4 * 2) = ta;
            }
        }
        unsigned int* sB = smw + (2 + buf) * (BUF_B / 4);
#pragma unroll
        for (int it = 0; it < 4; it++) {
            int idx = tid + it * 256;
            int r = idx >> 3, f4 = idx & 7;
            uint2 tb;
            tb.x = pack_h2(rb[it].x, rb[it].y);
            tb.y = pack_h2(rb[it].z, rb[it].w);
            *reinterpret_cast<uint2*>(sB + r * 20 + f4 * 2) = tb;
        }
    };
    auto mma_k = [&](int b, int ks) {
        const unsigned int baseA = smb + b * BUF_B;
        const unsigned int baseB = smb + (2 + b) * BUF_B;
        unsigned int af[4][4], bf[4][2];
#pragma unroll
        for (int mt = 0; mt < 4; mt++)
            ldsm_x4(af[mt],
                    baseA + (unsigned)(a_lane_b + mt * 1280 + ks * 32));
#pragma unroll
        for (int nt = 0; nt < 4; nt++)
            ldsm_x2(bf[nt],
                    baseB + (unsigned)(b_lane_b + nt * 640 + ks * 32));
#pragma unroll
        for (int mt = 0; mt < 4; mt++)
#pragma unroll
            for (int nt = 0; nt < 4; nt++)
                mma_f16(c[mt][nt], af[mt], bf[nt]);
    };

    load_regs(0);
    store_regs(0);
    __syncthreads();

#pragma unroll 1
    for (int kc = 0; kc < 8; kc++) {
        const int b = kc & 1;
        if (kc < 7) load_regs(kc + 1);     // LDGs in flight during full chunk
        mma_k(b, 0);
        mma_k(b, 1);
        if (kc < 7) store_regs(b ^ 1);     // store after max LDG cover
        __syncthreads();
    }

    // ---- stage accumulators in smem (128 x 132) ----
    float* stage = smf;
#pragma unroll
    for (int mt = 0; mt < 4; mt++) {
#pragma unroll
        for (int nt = 0; nt < 4; nt++) {
            int row = warp_m * 64 + mt * 16 + qr;
            int col = warp_n * 32 + nt * 8 + qc * 2;
            *reinterpret_cast<float2*>(stage + row * 132 + col) =
                make_float2(c[mt][nt][0], c[mt][nt][1]);
            *reinterpret_cast<float2*>(stage + (row + 8) * 132 + col) =
                make_float2(c[mt][nt][2], c[mt][nt][3]);
        }
    }
    __syncthreads();

    if (act == 3) {
        // fused logits: logits[m][h] += sum_n relu(h2_mn) * Wb3[h][n]/sqrt(d)
        float* sW3 = smf + 128 * 132;          // 8 x 128
        float* sb = sW3 + 1024;                // 128
        for (int i = tid; i < 1024; i += 256)
            sW3[i] = Wb3[(i >> 7) * 256 + n0 + (i & 127)];
        if (tid < 128) sb[tid] = bias[n0 + tid];
        __syncthreads();

        int row = tid >> 1, half = tid & 1;
        int m = m0 + row;
        float acc[NHD];
#pragma unroll
        for (int h = 0; h < NHD; h++) acc[h] = 0.f;
        const float* srow = smf + row * 132 + half * 64;
        const float* brow = sb + half * 64;
        const float* wrow = sW3 + half * 64;
#pragma unroll 8
        for (int cc = 0; cc < 64; cc++) {
            float v = fmaxf(srow[cc] + brow[cc], 0.f);
#pragma unroll
            for (int h = 0; h < NHD; h++) acc[h] += v * wrow[h * 128 + cc];
        }
#pragma unroll
        for (int h = 0; h < NHD; h++)
            atomicAdd(&logits[(size_t)m * NHD + h],
                      acc[h] * 0.17677669529663687f);
        return;
    }

    // ---- fused epilogue, coalesced (float4 or half2x2) ----
#pragma unroll 4
    for (int i = 0; i < 16; i++) {
        int idx = i * 256 + tid;
        int row = idx >> 5;
        int col = (idx & 31) * 4;
        int m = m0 + row, n = n0 + col;
        if (m < M) {
            float4 v = *reinterpret_cast<float4*>(stage + row * 132 + col);
            if (bias) {
                float4 bv = *reinterpret_cast<const float4*>(bias + n);
                v.x += bv.x; v.y += bv.y; v.z += bv.z; v.w += bv.w;
            }
            if (add1) {
                float4 a = *reinterpret_cast<const float4*>(
                    add1 + (size_t)idx1[m] * 256 + n);
                v.x += a.x; v.y += a.y; v.z += a.z; v.w += a.w;
            }
            if (add2) {
                float4 a = *reinterpret_cast<const float4*>(
                    add2 + (size_t)idx2[m] * 256 + n);
                v.x += a.x; v.y += a.y; v.z += a.z; v.w += a.w;
            }
            if (act == 1) {
                v.x = fmaxf(v.x, 0.f); v.y = fmaxf(v.y, 0.f);
                v.z = fmaxf(v.z, 0.f); v.w = fmaxf(v.w, 0.f);
            } else if (act == 2) {
                v.x = gelu_f(v.x); v.y = gelu_f(v.y);
                v.z = gelu_f(v.z); v.w = gelu_f(v.w);
            }
            if (CHALF) {
                __half* Ch = (__half*)Cv;
                uint2 o;
                o.x = pack_h2(v.x, v.y);
                o.y = pack_h2(v.z, v.w);
                *reinterpret_cast<uint2*>(Ch + (size_t)m * 256 + n) = o;
            } else {
                float* Cf = (float*)Cv;
                *reinterpret_cast<float4*>(Cf + (size_t)m * 256 + n) = v;
            }
        }
    }
}

// ---------------- logits init: bb3 broadcast * 1/sqrt(d) -------------------
__global__ void k_initlog(const float* __restrict__ bb3,
                          float* __restrict__ logits) {
    int i = blockIdx.x * 256 + threadIdx.x;
    if (i < EE * NHD)
        logits[i] = __ldg(bb3 + (i & 7)) * 0.17677669529663687f;
}

// ---------------- index dtype sniff + normalize ----------------------------
__global__ void k_sniff(const int* __restrict__ buf) {
    __shared__ int nz;
    if (threadIdx.x == 0) nz = 0;
    __syncthreads();
    int w = buf[threadIdx.x * 2 + 1];
    if (w != 0) atomicOr(&nz, 1);
    __syncthreads();
    if (threadIdx.x == 0) g_is64 = nz ? 0 : 1;
}

__global__ void k_convert(const void* __restrict__ buf,
                          int* __restrict__ dst, int* __restrict__ src) {
    int e = blockIdx.x * 256 + threadIdx.x;
    if (e >= EE) return;
    if (g_is64) {
        const long long* p = (const long long*)buf;
        dst[e] = (int)p[e];
        src[e] = (int)p[EE + e];
    } else {
        const int* p = (const int*)buf;
        dst[e] = p[e];
        src[e] = p[EE + e];
    }
}

// ---------------- CSR build -------------------------------------------------
__global__ void k_zero(int* a, int* b, int n) {
    int i = blockIdx.x * blockDim.x + threadIdx.x;
    if (i < n) { a[i] = 0; b[i] = 0; }
}

__global__ void k_count(const int* __restrict__ dst, int* __restrict__ deg) {
    int e = blockIdx.x * 256 + threadIdx.x;
    if (e < EE) atomicAdd(&deg[dst[e]], 1);
}

__global__ void __launch_bounds__(1024) k_scan(
    const int* __restrict__ deg, int* __restrict__ off)
{
    __shared__ int ssum[1024];
    const int t = threadIdx.x;
    const int ITEMS = 10;
    int base = t * ITEMS;
    int loc[ITEMS];
    int s = 0;
#pragma unroll
    for (int i = 0; i < ITEMS; i++) {
        int v = (base + i < NN) ? deg[base + i] : 0;
        loc[i] = s;
        s += v;
    }
    ssum[t] = s;
    __syncthreads();
    for (int d = 1; d < 1024; d <<= 1) {
        int v = (t >= d) ? ssum[t - d] : 0;
        __syncthreads();
        if (t >= d) ssum[t] += v;
        __syncthreads();
    }
    int excl = (t == 0) ? 0 : ssum[t - 1];
#pragma unroll
    for (int i = 0; i < ITEMS; i++)
        if (base + i < NN) off[base + i] = excl + loc[i];
    if (t == 0) off[NN] = ssum[1023];
}

__global__ void k_fill(const int* __restrict__ dst,
                       const int* __restrict__ off, int* __restrict__ cur,
                       int* __restrict__ elist)
{
    int e = blockIdx.x * 256 + threadIdx.x;
    if (e < EE) {
        int d = dst[e];
        int p = off[d] + atomicAdd(&cur[d], 1);
        elist[p] = e;
    }
}

// ---------------- per-node softmax + weighted aggregation ------------------
__global__ void __launch_bounds__(256) k_softmax_agg(
    const float* __restrict__ logits, const float* __restrict__ V,
    const int* __restrict__ off, const int* __restrict__ elist,
    float* __restrict__ agg)
{
    int n = blockIdx.x;
    int tid = threadIdx.x;
    int lane = tid & 31;
    int w = tid >> 5;

    int s = off[n];
    int deg = off[n + 1] - s;
    if (deg == 0) { agg[(size_t)n * HH + tid] = 0.f; return; }

    __shared__ float s_m[NHD], s_d[NHD];
    __shared__ int s_eid[64];

    float mx = -INFINITY;
    for (int i = lane; i < deg; i += 32)
        mx = fmaxf(mx, logits[(size_t)elist[s + i] * NHD + w]);
#pragma unroll
    for (int o = 16; o; o >>= 1) mx = fmaxf(mx, __shfl_xor_sync(0xffffffffu, mx, o));
    float sum = 0.f;
    for (int i = lane; i < deg; i += 32)
        sum += expf(logits[(size_t)elist[s + i] * NHD + w] - mx);
#pragma unroll
    for (int o = 16; o; o >>= 1) sum += __shfl_xor_sync(0xffffffffu, sum, o);
    if (lane == 0) { s_m[w] = mx; s_d[w] = sum; }
    __syncthreads();

    float m_h = s_m[w];
    float inv_d = 1.0f / s_d[w];

    float acc = 0.f;
    for (int c0 = 0; c0 < deg; c0 += 64) {
        int len = min(64, deg - c0);
        __syncthreads();
        if (tid < len) s_eid[tid] = elist[s + c0 + tid];
        __syncthreads();
        float a0 = 0.f, a1 = 0.f;
        if (lane < len)
            a0 = expf(logits[(size_t)s_eid[lane] * NHD + w] - m_h) * inv_d;
        if (32 + lane < len)
            a1 = expf(logits[(size_t)s_eid[32 + lane] * NHD + w] - m_h) * inv_d;
        for (int i = 0; i < len; i++) {
            float av = (i < 32) ? a0 : a1;
            float att = __shfl_sync(0xffffffffu, av, i & 31);
            acc += att * __ldg(V + (size_t)s_eid[i] * HH + tid);
        }
    }
    agg[(size_t)n * HH + tid] = acc;
}

// ---------------- launch ----------------------------------------------------
extern "C" void kernel_launch(void* const* d_in, const int* in_sizes, int n_in,
                              void* d_out, int out_size)
{
    const float* src_na = (const float*)d_in[0];
    const float* dst_na = (const float*)d_in[1];
    const float* ea     = (const float*)d_in[2];
    const void*  eidx   = d_in[3];
    const float* Wv1 = (const float*)d_in[4];
    const float* bv1 = (const float*)d_in[5];
    const float* Wv2 = (const float*)d_in[6];
    const float* bv2 = (const float*)d_in[7];
    const float* Wv3 = (const float*)d_in[8];
    const float* bv3 = (const float*)d_in[9];
    const float* Wb1 = (const float*)d_in[10];
    const float* bb1 = (const float*)d_in[11];
    const float* Wb2 = (const float*)d_in[12];
    const float* bb2 = (const float*)d_in[13];
    const float* Wb3 = (const float*)d_in[14];
    const float* bb3 = (const float*)d_in[15];
    const float* WO  = (const float*)d_in[16];

    float *pS1, *pT1, *pSv, *pe1, *pe2, *plog, *pagg;
    int *pdeg, *pcur, *poff, *pel, *pdst, *psrc;
    cudaGetSymbolAddress((void**)&pS1, g_S1);
    cudaGetSymbolAddress((void**)&pT1, g_T1);
    cudaGetSymbolAddress((void**)&pSv, g_Sv);
    cudaGetSymbolAddress((void**)&pe1, g_e1);
    cudaGetSymbolAddress((void**)&pe2, g_e2);
    cudaGetSymbolAddress((void**)&plog, g_logits);
    cudaGetSymbolAddress((void**)&pagg, g_agg);
    cudaGetSymbolAddress((void**)&pdeg, g_deg);
    cudaGetSymbolAddress((void**)&pcur, g_cur);
    cudaGetSymbolAddress((void**)&poff, g_off);
    cudaGetSymbolAddress((void**)&pel, g_elist);
    cudaGetSymbolAddress((void**)&pdst, g_dst);
    cudaGetSymbolAddress((void**)&psrc, g_src);

    cudaFuncSetAttribute(mma_gemm<false, false>,
        cudaFuncAttributeMaxDynamicSharedMemorySize, SMEM_BYTES);
    cudaFuncSetAttribute(mma_gemm<false, true>,
        cudaFuncAttributeMaxDynamicSharedMemorySize, SMEM_BYTES);
    cudaFuncSetAttribute(mma_gemm<true, false>,
        cudaFuncAttributeMaxDynamicSharedMemorySize, SMEM_BYTES);
    cudaFuncSetAttribute(mma_gemm<true, true>,
        cudaFuncAttributeMaxDynamicSharedMemorySize, SMEM_BYTES);

    dim3 gn((NN + 127) / 128, 2);   // 79 x 2
    dim3 ge(EE / 128, 2);           // 2500 x 2

    // 1-2: index normalize
    k_sniff<<<1, 128>>>((const int*)eidx);
    k_convert<<<(EE + 255) / 256, 256>>>(eidx, pdst, psrc);

    // 3-5: node precomputes (fp32 in/out -- consumed as epilogue adds)
    mma_gemm<false, false><<<gn, 256, SMEM_BYTES>>>(src_na, 256, Wb1, 768,
        nullptr, nullptr, nullptr, nullptr, nullptr, pS1, NN, 0, nullptr, nullptr);
    mma_gemm<false, false><<<gn, 256, SMEM_BYTES>>>(dst_na, 256, Wb1 + 512, 768,
        nullptr, nullptr, nullptr, nullptr, nullptr, pT1, NN, 0, nullptr, nullptr);
    mma_gemm<false, false><<<gn, 256, SMEM_BYTES>>>(src_na, 256, Wv1, 512,
        nullptr, nullptr, nullptr, nullptr, nullptr, pSv, NN, 0, nullptr, nullptr);

    // 6: h1 = relu(ea@Wb1_e^T + S1[src] + T1[dst] + bb1) -> fp16 pe1
    mma_gemm<false, true><<<ge, 256, SMEM_BYTES>>>(ea, 256, Wb1 + 256, 768, bb1,
        pS1, psrc, pT1, pdst, pe1, EE, 1, nullptr, nullptr);

    // 7-8: logits init, fused h2+logits (A = fp16 h1; h2 never materialized)
    k_initlog<<<(EE * NHD) / 256, 256>>>(bb3, plog);
    mma_gemm<true, false><<<ge, 256, SMEM_BYTES>>>(pe1, 256, Wb2, 256, bb2,
        nullptr, nullptr, nullptr, nullptr, nullptr, EE, 3, Wb3, plog);

    // 9: v1 = gelu(ea@Wv1_e^T + Sv[src] + bv1) -> fp16 pe2
    mma_gemm<false, true><<<ge, 256, SMEM_BYTES>>>(ea, 256, Wv1 + 256, 512, bv1,
        pSv, psrc, nullptr, nullptr, pe2, EE, 2, nullptr, nullptr);

    // 10-13: CSR build
    k_zero<<<(NN + 255) / 256, 256>>>(pdeg, pcur, NN);
    k_count<<<EE / 256, 256>>>(pdst, pdeg);
    k_scan<<<1, 1024>>>(pdeg, poff);
    k_fill<<<EE / 256, 256>>>(pdst, poff, pcur, pel);

    // 14: v2 = gelu(v1@Wv2^T + bv2)  fp16 -> fp16 pe1
    mma_gemm<true, true><<<ge, 256, SMEM_BYTES>>>(pe2, 256, Wv2, 256, bv2,
        nullptr, nullptr, nullptr, nullptr, pe1, EE, 2, nullptr, nullptr);
    // 15: V = v2@Wv3^T + bv3  fp16 -> fp32 pe2 (consumed by softmax_agg)
    mma_gemm<true, false><<<ge, 256, SMEM_BYTES>>>(pe1, 256, Wv3, 256, bv3,
        nullptr, nullptr, nullptr, nullptr, pe2, EE, 0, nullptr, nullptr);

    // 16: per-node softmax + aggregation
    k_softmax_agg<<<NN, 256>>>(plog, pe2, poff, pel, pagg);

    // 17: output projection (fp32 in/out)
    mma_gemm<false, false><<<gn, 256, SMEM_BYTES>>>(pagg, 256, WO, 256, nullptr,
        nullptr, nullptr, nullptr, nullptr, (float*)d_out, NN, 0,
        nullptr, nullptr);
}